// round 2
// baseline (speedup 1.0000x reference)
#include <cuda_runtime.h>
#include <math.h>

#define BB    16
#define CCH   512
#define NN    3136
#define NKK   49
#define HEADS 8
#define HD    64
#define JJ    392      // HEADS*NKK
#define HIDC  24
#define SCALE 0.125f

// ---------------- device scratch (static, no allocs) ----------------
__device__ float g_kvx[BB*NKK*CCH];          // (b, m, c)
__device__ float g_kv [BB*NKK*1024];         // (b, m, 2C)
__device__ float g_Wqk[BB*CCH*JJ];           // (b, cin, j)
__device__ float g_Wvp[BB*JJ*CCH];           // (b, j, cout)
__device__ float g_attn[(size_t)BB*NN*JJ];   // (b, n, j): scores -> softmax -> DLA out
__device__ float g_hid1[(size_t)BB*NN*HIDC*NKK];
__device__ float g_hid2[(size_t)BB*NN*HIDC*NKK];
__device__ float g_part[BB*3*64*2];
__device__ float g_ab1[BB*HIDC*2];
__device__ float g_ab2[BB*HIDC*2];
__device__ float g_ab3[BB*HEADS*2];

__device__ __forceinline__ float swishf(float x) {
    return x / (1.f + __expf(-x));
}

// ---------------- 1. depthwise 8x8/8 downsample ----------------
__global__ void k_down(const float* __restrict__ x, const float* __restrict__ down_w) {
    int bc = blockIdx.x;            // b*512 + c
    int c  = bc & 511;
    int b  = bc >> 9;
    __shared__ float plane[3136];
    __shared__ float w[64];
    const float* xp = x + (size_t)bc * 3136;
    for (int i = threadIdx.x; i < 3136; i += 256) plane[i] = xp[i];
    if (threadIdx.x < 64) w[threadIdx.x] = down_w[c*64 + threadIdx.x];
    __syncthreads();
    if (threadIdx.x < 49) {
        int my = threadIdx.x / 7, mx = threadIdx.x % 7;
        float s = 0.f;
        #pragma unroll
        for (int i = 0; i < 8; i++)
            #pragma unroll
            for (int j = 0; j < 8; j++)
                s += plane[(my*8+i)*56 + mx*8 + j] * w[i*8+j];
        g_kvx[(b*49 + threadIdx.x)*512 + c] = s;
    }
}

// ---------------- 2. kv = kvx @ kv_w  (784 x 1024, K=512) ----------------
__global__ void k_kv(const float* __restrict__ kv_w) {
    int b  = blockIdx.x / 7;
    int m0 = (blockIdx.x % 7) * 7;
    __shared__ float a[7][512];
    for (int i = threadIdx.x; i < 7*512; i += 256)
        a[i >> 9][i & 511] = g_kvx[(b*49 + m0 + (i >> 9))*512 + (i & 511)];
    __syncthreads();
    for (int oB = 0; oB < 1024; oB += 256) {
        int o = oB + threadIdx.x;
        float acc[7] = {0,0,0,0,0,0,0};
        for (int c = 0; c < 512; c++) {
            float w = kv_w[c*1024 + o];
            #pragma unroll
            for (int mm = 0; mm < 7; mm++) acc[mm] += a[mm][c] * w;
        }
        #pragma unroll
        for (int mm = 0; mm < 7; mm++)
            g_kv[(b*49 + m0 + mm)*1024 + o] = acc[mm];
    }
}

// ---------------- 3. Wqk[b,cin,h*49+m] = SCALE * q_w[cin,h*64+:] . k[b,h,m,:] ----------------
__global__ void k_wqk(const float* __restrict__ q_w) {
    int b = blockIdx.x >> 3, h = blockIdx.x & 7;
    __shared__ float ks[49][64];
    for (int i = threadIdx.x; i < 49*64; i += 256)
        ks[i >> 6][i & 63] = g_kv[(b*49 + (i >> 6))*1024 + h*64 + (i & 63)];
    __syncthreads();
    for (int cinB = 0; cinB < 512; cinB += 256) {
        int cin = cinB + threadIdx.x;
        const float* qr = q_w + cin*512 + h*64;
        for (int mc = 0; mc < 49; mc += 7) {
            float acc[7] = {0,0,0,0,0,0,0};
            for (int d = 0; d < 64; d++) {
                float qd = qr[d];
                #pragma unroll
                for (int mm = 0; mm < 7; mm++) acc[mm] += qd * ks[mc+mm][d];
            }
            #pragma unroll
            for (int mm = 0; mm < 7; mm++)
                g_Wqk[(b*512 + cin)*392 + h*49 + mc + mm] = acc[mm] * SCALE;
        }
    }
}

// ---------------- 4. Wvp[b,h*49+m,cout] = v[b,h,m,:] . proj_w[h*64+:,cout] ----------------
__global__ void k_wvp(const float* __restrict__ proj_w) {
    int b = blockIdx.x >> 3, h = blockIdx.x & 7;
    __shared__ float vs[49][64];
    for (int i = threadIdx.x; i < 49*64; i += 256)
        vs[i >> 6][i & 63] = g_kv[(b*49 + (i >> 6))*1024 + 512 + h*64 + (i & 63)];
    __syncthreads();
    int t = threadIdx.x;
    for (int mc = 0; mc < 49; mc += 7) {
        float acc[7][2] = {{0}};
        for (int d = 0; d < 64; d++) {
            float w0 = proj_w[(h*64+d)*512 + t];
            float w1 = proj_w[(h*64+d)*512 + 256 + t];
            #pragma unroll
            for (int mm = 0; mm < 7; mm++) {
                float vv = vs[mc+mm][d];
                acc[mm][0] += vv * w0;
                acc[mm][1] += vv * w1;
            }
        }
        #pragma unroll
        for (int mm = 0; mm < 7; mm++) {
            int j = h*49 + mc + mm;
            g_Wvp[(b*392 + j)*512 + t]       = acc[mm][0];
            g_Wvp[(b*392 + j)*512 + 256 + t] = acc[mm][1];
        }
    }
}

// ---------------- 5. GEMM1: attn[b,n,j] = x[b,:,n].Wqk[b,:,j] + rel_bias ----------------
// tile 128(n) x 56(j), K-tile 16; 224 threads, micro 4x8
__global__ void k_gemm1(const float* __restrict__ x, const float* __restrict__ rel_bias) {
    int b = blockIdx.z, nt0 = blockIdx.y*128, jt0 = blockIdx.x*56;
    __shared__ float As[16][128];
    __shared__ float Bs[16][56];
    int t  = threadIdx.x;
    int jg = t % 7, ng = t / 7;     // ng 0..31
    float acc[4][8] = {{0}};
    const float* xb = x     + (size_t)b*512*3136;
    const float* wb = g_Wqk + (size_t)b*512*392;
    for (int k0 = 0; k0 < 512; k0 += 16) {
        for (int i = t; i < 2048; i += 224) {
            int kk = i >> 7, nn = i & 127;
            int n = nt0 + nn;
            As[kk][nn] = (n < 3136) ? xb[(k0+kk)*3136 + n] : 0.f;
        }
        for (int i = t; i < 896; i += 224) {
            int kk = i / 56, jj = i % 56;
            Bs[kk][jj] = wb[(k0+kk)*392 + jt0 + jj];
        }
        __syncthreads();
        #pragma unroll
        for (int kk = 0; kk < 16; kk++) {
            float af[4], bf[8];
            #pragma unroll
            for (int i = 0; i < 4; i++) af[i] = As[kk][ng*4+i];
            #pragma unroll
            for (int i = 0; i < 8; i++) bf[i] = Bs[kk][jg*8+i];
            #pragma unroll
            for (int i = 0; i < 4; i++)
                #pragma unroll
                for (int j2 = 0; j2 < 8; j2++) acc[i][j2] += af[i]*bf[j2];
        }
        __syncthreads();
    }
    #pragma unroll
    for (int i = 0; i < 4; i++) {
        int n = nt0 + ng*4 + i;
        if (n >= 3136) continue;
        #pragma unroll
        for (int j2 = 0; j2 < 8; j2++) {
            int j = jt0 + jg*8 + j2;
            int m = j - (j/49)*49;
            g_attn[((size_t)b*3136 + n)*392 + j] = acc[i][j2] + rel_bias[n*49 + m];
        }
    }
}

// ---------------- 6. softmax over m (49) per (b,n,h) ----------------
__global__ void k_softmax() {
    __shared__ float sh[392];
    __shared__ float mx[8], sm[8];
    size_t row = (size_t)blockIdx.x * 392;
    int t = threadIdx.x;
    float v = g_attn[row + t];
    sh[t] = v;
    __syncthreads();
    if (t < 8) {
        float m = -1e30f;
        for (int i = 0; i < 49; i++) m = fmaxf(m, sh[t*49+i]);
        mx[t] = m;
    }
    __syncthreads();
    float e = __expf(v - mx[t/49]);
    sh[t] = e;
    __syncthreads();
    if (t < 8) {
        float s = 0.f;
        for (int i = 0; i < 49; i++) s += sh[t*49+i];
        sm[t] = 1.f / s;
    }
    __syncthreads();
    g_attn[row + t] = e * sm[t/49];
}

// ---------------- 7. DLA expand 1x1: 8 -> 24 channels ----------------
__global__ void k_expand(const float* __restrict__ expand_w) {
    int b = blockIdx.x / 392, n0 = (blockIdx.x % 392) * 8;
    __shared__ float a[8*392];
    __shared__ float w[192];
    int t = threadIdx.x;
    for (int i = t; i < 8*392; i += 392)
        a[i] = g_attn[((size_t)b*3136 + n0)*392 + i];
    if (t < 192) w[t] = expand_w[t];
    __syncthreads();
    int nl = t / 49, m = t % 49;
    float in[8];
    #pragma unroll
    for (int h = 0; h < 8; h++) in[h] = a[nl*392 + h*49 + m];
    size_t obase = (((size_t)b*3136 + n0 + nl)*24)*49 + m;
    #pragma unroll
    for (int c = 0; c < 24; c++) {
        float o = 0.f;
        #pragma unroll
        for (int h = 0; h < 8; h++) o += in[h] * w[c*8+h];
        g_hid1[obase + (size_t)c*49] = o;
    }
}

// ---------------- stats: per (b,group) sum/sumsq, 2-stage deterministic ----------------
__global__ void k_stats_part(const float* __restrict__ buf, int CH, int CPG) {
    int s = blockIdx.x, g = blockIdx.y, b = blockIdx.z;
    int G = gridDim.y;
    int gsz = CPG*49;
    float smv = 0.f, sq = 0.f;
    for (int n = s*49; n < s*49 + 49; n++) {
        const float* p = buf + (((size_t)b*3136 + n)*CH + g*CPG)*49;
        for (int r = threadIdx.x; r < gsz; r += 256) {
            float v = p[r];
            smv += v; sq += v*v;
        }
    }
    __shared__ float rs[256], rq[256];
    int t = threadIdx.x;
    rs[t] = smv; rq[t] = sq;
    __syncthreads();
    for (int st = 128; st; st >>= 1) {
        if (t < st) { rs[t] += rs[t+st]; rq[t] += rq[t+st]; }
        __syncthreads();
    }
    if (!t) {
        int o = ((b*G + g)*64 + s)*2;
        g_part[o] = rs[0]; g_part[o+1] = rq[0];
    }
}

__global__ void k_stats_final(const float* __restrict__ gs, const float* __restrict__ gb,
                              float* __restrict__ ab, int G, int CPG) {
    int t = threadIdx.x;
    if (t >= 16*G) return;
    int b = t / G, g = t % G;
    float smv = 0.f, sq = 0.f;
    for (int s = 0; s < 64; s++) {
        smv += g_part[((b*G+g)*64 + s)*2];
        sq  += g_part[((b*G+g)*64 + s)*2 + 1];
    }
    float cnt  = (float)CPG * 3136.f * 49.f;
    float mean = smv / cnt;
    float var  = sq / cnt - mean*mean;
    float rstd = rsqrtf(var + 1e-5f);
    int CHt = G*CPG;
    for (int c0 = 0; c0 < CPG; c0++) {
        int c = g*CPG + c0;
        float A = rstd * gs[c];
        ab[(b*CHt + c)*2]     = A;
        ab[(b*CHt + c)*2 + 1] = gb[c] - mean*A;
    }
}

// ---------------- 8. depthwise 3x3 SAME on (3136 x 49) image, norm1+swish fused on load ----------------
__global__ void k_dw(const float* __restrict__ dw_w) {
    int nt = blockIdx.x, c = blockIdx.y, b = blockIdx.z;
    int n0 = nt * 16;
    __shared__ float s[18][51];
    __shared__ float w[9];
    float A  = g_ab1[(b*24 + c)*2];
    float Bc = g_ab1[(b*24 + c)*2 + 1];
    int t = threadIdx.x;
    if (t < 9) w[t] = dw_w[c*9 + t];
    for (int i = t; i < 18*51; i += 256) {
        int r = i / 51, cc = i % 51;
        int n = n0 - 1 + r, m = cc - 1;
        float v = 0.f;
        if (n >= 0 && n < 3136 && m >= 0 && m < 49) {
            float xx = g_hid1[(((size_t)b*3136 + n)*24 + c)*49 + m];
            v = swishf(A*xx + Bc);
        }
        s[r][cc] = v;
    }
    __syncthreads();
    for (int o = t; o < 16*49; o += 256) {
        int ny = o / 49, m = o % 49;
        float acc = 0.f;
        #pragma unroll
        for (int dy = 0; dy < 3; dy++)
            #pragma unroll
            for (int dx = 0; dx < 3; dx++)
                acc += s[ny+dy][m+dx] * w[dy*3+dx];
        g_hid2[(((size_t)b*3136 + n0 + ny)*24 + c)*49 + m] = acc;
    }
}

// ---------------- 9. reduce 1x1: 24 -> 8, norm2+swish fused on load ----------------
__global__ void k_reduce(const float* __restrict__ reduce_w) {
    int b = blockIdx.x / 392, n0 = (blockIdx.x % 392) * 8;
    __shared__ float w[192];
    __shared__ float A2s[24], B2s[24];
    int t = threadIdx.x;
    if (t < 192) w[t] = reduce_w[t];
    if (t < 24) { A2s[t] = g_ab2[(b*24+t)*2]; B2s[t] = g_ab2[(b*24+t)*2+1]; }
    __syncthreads();
    int nl = t / 49, m = t % 49;
    int n = n0 + nl;
    float in[24];
    size_t ibase = (((size_t)b*3136 + n)*24)*49 + m;
    #pragma unroll
    for (int c = 0; c < 24; c++) {
        float xx = g_hid2[ibase + (size_t)c*49];
        in[c] = swishf(A2s[c]*xx + B2s[c]);
    }
    size_t obase = ((size_t)b*3136 + n)*392 + m;
    #pragma unroll
    for (int h = 0; h < 8; h++) {
        float o = 0.f;
        #pragma unroll
        for (int c = 0; c < 24; c++) o += in[c] * w[h*24+c];
        g_attn[obase + h*49] = o;
    }
}

// ---------------- 10. GEMM2: out[b,n,co] = norm3(attnF[b,n,:]) . Wvp[b,:,co] + proj_b ----------------
// tile 128(n) x 64(co), K=392 in steps of 16; 256 threads, micro 4x8
__global__ void k_gemm2(const float* __restrict__ proj_b, float* __restrict__ out) {
    int b = blockIdx.z, nt0 = blockIdx.y*128, ct0 = blockIdx.x*64;
    __shared__ float As[128][17];
    __shared__ float Bs[16][64];
    __shared__ float A3s[8], B3s[8];
    int t = threadIdx.x;
    if (t < 8) { A3s[t] = g_ab3[(b*8+t)*2]; B3s[t] = g_ab3[(b*8+t)*2+1]; }
    __syncthreads();
    int cg = t & 7, ng = t >> 3;    // ng 0..31
    float acc[4][8] = {{0}};
    const float* ap = g_attn + (size_t)b*3136*392;
    const float* wb = g_Wvp  + (size_t)b*392*512;
    for (int k0 = 0; k0 < 392; k0 += 16) {
        for (int i = t; i < 2048; i += 256) {
            int nn = i >> 4, kk = i & 15;
            int n = nt0 + nn, j = k0 + kk;
            float v = 0.f;
            if (n < 3136 && j < 392) {
                int h = j / 49;
                v = ap[(size_t)n*392 + j] * A3s[h] + B3s[h];
            }
            As[nn][kk] = v;
        }
        for (int i = t; i < 1024; i += 256) {
            int kk = i >> 6, cc = i & 63;
            int j = k0 + kk;
            Bs[kk][cc] = (j < 392) ? wb[(size_t)j*512 + ct0 + cc] : 0.f;
        }
        __syncthreads();
        #pragma unroll
        for (int kk = 0; kk < 16; kk++) {
            float af[4], bf[8];
            #pragma unroll
            for (int i = 0; i < 4; i++) af[i] = As[ng*4+i][kk];
            #pragma unroll
            for (int i = 0; i < 8; i++) bf[i] = Bs[kk][cg*8+i];
            #pragma unroll
            for (int i = 0; i < 4; i++)
                #pragma unroll
                for (int j2 = 0; j2 < 8; j2++) acc[i][j2] += af[i]*bf[j2];
        }
        __syncthreads();
    }
    #pragma unroll
    for (int i = 0; i < 4; i++) {
        int n = nt0 + ng*4 + i;
        if (n >= 3136) continue;
        #pragma unroll
        for (int j2 = 0; j2 < 8; j2++) {
            int c = ct0 + cg*8 + j2;
            out[((size_t)b*3136 + n)*512 + c] = acc[i][j2] + proj_b[c];
        }
    }
}

// ---------------- launcher ----------------
extern "C" void kernel_launch(void* const* d_in, const int* in_sizes, int n_in,
                              void* d_out, int out_size) {
    const float* x        = (const float*)d_in[0];
    const float* q_w      = (const float*)d_in[1];
    const float* down_w   = (const float*)d_in[2];
    const float* kv_w     = (const float*)d_in[3];
    const float* proj_w   = (const float*)d_in[4];
    const float* proj_b   = (const float*)d_in[5];
    const float* rel_bias = (const float*)d_in[6];
    const float* expand_w = (const float*)d_in[7];
    const float* gn1_s    = (const float*)d_in[8];
    const float* gn1_b    = (const float*)d_in[9];
    const float* dw_w     = (const float*)d_in[10];
    const float* gn2_s    = (const float*)d_in[11];
    const float* gn2_b    = (const float*)d_in[12];
    const float* reduce_w = (const float*)d_in[13];
    const float* gn3_s    = (const float*)d_in[14];
    const float* gn3_b    = (const float*)d_in[15];
    float* out = (float*)d_out;

    float *ab1, *ab2, *ab3;
    cudaGetSymbolAddress((void**)&ab1, g_ab1);
    cudaGetSymbolAddress((void**)&ab2, g_ab2);
    cudaGetSymbolAddress((void**)&ab3, g_ab3);
    float* hid1p; cudaGetSymbolAddress((void**)&hid1p, g_hid1);
    float* hid2p; cudaGetSymbolAddress((void**)&hid2p, g_hid2);
    float* attnp; cudaGetSymbolAddress((void**)&attnp, g_attn);

    k_down<<<BB*CCH, 256>>>(x, down_w);
    k_kv  <<<BB*7,  256>>>(kv_w);
    k_wqk <<<BB*8,  256>>>(q_w);
    k_wvp <<<BB*8,  256>>>(proj_w);
    k_gemm1<<<dim3(7, 25, BB), 224>>>(x, rel_bias);
    k_softmax<<<BB*NN, 392>>>();
    k_expand<<<BB*392, 392>>>(expand_w);
    k_stats_part<<<dim3(64, 3, BB), 256>>>(hid1p, 24, 8);
    k_stats_final<<<1, 64>>>(gn1_s, gn1_b, ab1, 3, 8);
    k_dw<<<dim3(196, 24, BB), 256>>>(dw_w);
    k_stats_part<<<dim3(64, 3, BB), 256>>>(hid2p, 24, 8);
    k_stats_final<<<1, 64>>>(gn2_s, gn2_b, ab2, 3, 8);
    k_reduce<<<BB*392, 392>>>(reduce_w);
    k_stats_part<<<dim3(64, 1, BB), 256>>>(attnp, 8, 8);
    k_stats_final<<<1, 64>>>(gn3_s, gn3_b, ab3, 1, 8);
    k_gemm2<<<dim3(8, 25, BB), 256>>>(proj_b, out);
}

// round 3
// speedup vs baseline: 1.3955x; 1.3955x over previous
#include <cuda_runtime.h>
#include <math.h>
#include <stdint.h>

#define BB    16
#define CCH   512
#define NN    3136
#define NKK   49
#define HEADS 8
#define JJ    392      // HEADS*NKK
#define HIDC  24
#define SCALE 0.125f

// ---------------- device scratch ----------------
__device__ float g_kvx[BB*NKK*CCH];
__device__ float g_kv [BB*NKK*1024];
__device__ float g_Wqk[BB*CCH*JJ];
__device__ float g_Wvp[BB*JJ*CCH];
__device__ float g_attn[(size_t)BB*NN*JJ];
__device__ float g_hid1[(size_t)BB*NN*HIDC*NKK];
__device__ float g_hid2[(size_t)BB*NN*HIDC*NKK];
__device__ float g_part1[BB*3*392*2];
__device__ float g_part2[BB*24*196*2];
__device__ float g_part3[BB*392*2];
__device__ float g_ab1[BB*HIDC*2];
__device__ float g_ab2[BB*HIDC*2];
__device__ float g_ab3[BB*HEADS*2];

__device__ __forceinline__ float swishf(float x) { return x / (1.f + __expf(-x)); }

__device__ __forceinline__ uint32_t f2tf32(float x) {
    uint32_t r;
    asm("cvt.rna.tf32.f32 %0, %1;" : "=r"(r) : "f"(x));
    return r;
}

__device__ __forceinline__ void mma_tf32(float* c, const uint32_t* a, const uint32_t* b) {
    asm volatile(
        "mma.sync.aligned.m16n8k8.row.col.f32.tf32.tf32.f32 "
        "{%0,%1,%2,%3}, {%4,%5,%6,%7}, {%8,%9}, {%0,%1,%2,%3};"
        : "+f"(c[0]), "+f"(c[1]), "+f"(c[2]), "+f"(c[3])
        : "r"(a[0]), "r"(a[1]), "r"(a[2]), "r"(a[3]), "r"(b[0]), "r"(b[1]));
}

// ---------------- 1. depthwise 8x8/8 downsample ----------------
__global__ void k_down(const float* __restrict__ x, const float* __restrict__ down_w) {
    int bc = blockIdx.x, c = bc & 511, b = bc >> 9;
    __shared__ float plane[3136];
    __shared__ float w[64];
    const float* xp = x + (size_t)bc * 3136;
    for (int i = threadIdx.x; i < 3136; i += 256) plane[i] = xp[i];
    if (threadIdx.x < 64) w[threadIdx.x] = down_w[c*64 + threadIdx.x];
    __syncthreads();
    if (threadIdx.x < 49) {
        int my = threadIdx.x / 7, mx = threadIdx.x % 7;
        float s = 0.f;
        #pragma unroll
        for (int i = 0; i < 8; i++)
            #pragma unroll
            for (int j = 0; j < 8; j++)
                s += plane[(my*8+i)*56 + mx*8 + j] * w[i*8+j];
        g_kvx[(b*49 + threadIdx.x)*512 + c] = s;
    }
}

// ---------------- 2. kv = kvx @ kv_w ----------------
__global__ void k_kv(const float* __restrict__ kv_w) {
    int b = blockIdx.z, m0 = blockIdx.y * 7, oc = blockIdx.x;
    __shared__ float a[7][512];
    for (int i = threadIdx.x; i < 7*512; i += 256)
        a[i >> 9][i & 511] = g_kvx[(b*49 + m0 + (i >> 9))*512 + (i & 511)];
    __syncthreads();
    int o = oc*256 + threadIdx.x;
    float acc[7] = {0,0,0,0,0,0,0};
    for (int c = 0; c < 512; c++) {
        float w = kv_w[c*1024 + o];
        #pragma unroll
        for (int mm = 0; mm < 7; mm++) acc[mm] += a[mm][c] * w;
    }
    #pragma unroll
    for (int mm = 0; mm < 7; mm++)
        g_kv[(b*49 + m0 + mm)*1024 + o] = acc[mm];
}

// ---------------- 3. Wqk ----------------
__global__ void k_wqk(const float* __restrict__ q_w) {
    int b = blockIdx.z, h = blockIdx.y, half = blockIdx.x;
    __shared__ float ks[49][64];
    for (int i = threadIdx.x; i < 49*64; i += 256)
        ks[i >> 6][i & 63] = g_kv[(b*49 + (i >> 6))*1024 + h*64 + (i & 63)];
    __syncthreads();
    int cin = half*256 + threadIdx.x;
    const float* qr = q_w + cin*512 + h*64;
    for (int mc = 0; mc < 49; mc += 7) {
        float acc[7] = {0,0,0,0,0,0,0};
        for (int d = 0; d < 64; d++) {
            float qd = qr[d];
            #pragma unroll
            for (int mm = 0; mm < 7; mm++) acc[mm] += qd * ks[mc+mm][d];
        }
        #pragma unroll
        for (int mm = 0; mm < 7; mm++)
            g_Wqk[(b*512 + cin)*392 + h*49 + mc + mm] = acc[mm] * SCALE;
    }
}

// ---------------- 4. Wvp ----------------
__global__ void k_wvp(const float* __restrict__ proj_w) {
    int b = blockIdx.z, h = blockIdx.y, mc = blockIdx.x * 7;
    __shared__ float vs[7][64];
    for (int i = threadIdx.x; i < 7*64; i += 256)
        vs[i >> 6][i & 63] = g_kv[(b*49 + mc + (i >> 6))*1024 + 512 + h*64 + (i & 63)];
    __syncthreads();
    int t = threadIdx.x;
    float acc[7][2] = {{0}};
    for (int d = 0; d < 64; d++) {
        float w0 = proj_w[(h*64+d)*512 + t];
        float w1 = proj_w[(h*64+d)*512 + 256 + t];
        #pragma unroll
        for (int mm = 0; mm < 7; mm++) {
            float vv = vs[mm][d];
            acc[mm][0] += vv * w0;
            acc[mm][1] += vv * w1;
        }
    }
    #pragma unroll
    for (int mm = 0; mm < 7; mm++) {
        int j = h*49 + mc + mm;
        g_Wvp[(b*392 + j)*512 + t]       = acc[mm][0];
        g_Wvp[(b*392 + j)*512 + 256 + t] = acc[mm][1];
    }
}

// ---------------- 5. GEMM1 (tf32x3 tensor): attn = x^T . Wqk + rel_bias ----------------
// block tile 128n x 56j, k-tile 16; 8 warps, warp tile 16n x 56j
#define PADA 132
#define PADB 72
__global__ __launch_bounds__(256) void k_gemm1(const float* __restrict__ x,
                                               const float* __restrict__ rel_bias) {
    int b = blockIdx.z, nt0 = blockIdx.y*128, jt0 = blockIdx.x*56;
    __shared__ uint32_t Ah[16*PADA], Al[16*PADA], Bh[16*PADB], Bl[16*PADB];
    int t = threadIdx.x, w = t >> 5, lane = t & 31;
    float acc[7][4];
    #pragma unroll
    for (int i = 0; i < 7; i++)
        #pragma unroll
        for (int k = 0; k < 4; k++) acc[i][k] = 0.f;
    const float* xb = x     + (size_t)b*512*3136;
    const float* wb = g_Wqk + (size_t)b*512*392;
    for (int k0 = 0; k0 < 512; k0 += 16) {
        #pragma unroll
        for (int r = 0; r < 8; r++) {
            int i = t + 256*r, kk = i >> 7, nn = i & 127;
            int n = nt0 + nn;
            float v = (n < 3136) ? xb[(size_t)(k0+kk)*3136 + n] : 0.f;
            uint32_t hi = f2tf32(v);
            Ah[kk*PADA + nn] = hi;
            Al[kk*PADA + nn] = f2tf32(v - __uint_as_float(hi));
        }
        for (int i = t; i < 896; i += 256) {
            int kk = i / 56, jj = i % 56;
            float v = wb[(size_t)(k0+kk)*392 + jt0 + jj];
            uint32_t hi = f2tf32(v);
            Bh[kk*PADB + jj] = hi;
            Bl[kk*PADB + jj] = f2tf32(v - __uint_as_float(hi));
        }
        __syncthreads();
        #pragma unroll
        for (int kc = 0; kc < 2; kc++) {
            int kb = kc*8;
            uint32_t ah[4], al[4];
            int row = w*16 + (lane >> 2), col = kb + (lane & 3);
            ah[0] = Ah[col*PADA + row];     al[0] = Al[col*PADA + row];
            ah[1] = Ah[col*PADA + row+8];   al[1] = Al[col*PADA + row+8];
            ah[2] = Ah[(col+4)*PADA + row];   al[2] = Al[(col+4)*PADA + row];
            ah[3] = Ah[(col+4)*PADA + row+8]; al[3] = Al[(col+4)*PADA + row+8];
            #pragma unroll
            for (int ju = 0; ju < 7; ju++) {
                uint32_t bh[2], bl[2];
                int jc = ju*8 + (lane >> 2), kr = kb + (lane & 3);
                bh[0] = Bh[kr*PADB + jc];     bl[0] = Bl[kr*PADB + jc];
                bh[1] = Bh[(kr+4)*PADB + jc]; bl[1] = Bl[(kr+4)*PADB + jc];
                mma_tf32(acc[ju], ah, bh);
                mma_tf32(acc[ju], ah, bl);
                mma_tf32(acc[ju], al, bh);
            }
        }
        __syncthreads();
    }
    int row = nt0 + w*16 + (lane >> 2);
    #pragma unroll
    for (int ju = 0; ju < 7; ju++) {
        int j0 = jt0 + ju*8 + 2*(lane & 3);
        #pragma unroll
        for (int half = 0; half < 2; half++) {
            int n = row + half*8;
            if (n >= 3136) continue;
            #pragma unroll
            for (int e = 0; e < 2; e++) {
                int j = j0 + e;
                int m = j - (j/49)*49;
                g_attn[((size_t)b*3136 + n)*392 + j] = acc[ju][half*2 + e] + rel_bias[n*49 + m];
            }
        }
    }
}

// ---------------- 6. fused softmax + expand(8->24) + gn1 partials ----------------
__global__ __launch_bounds__(256) void k_sm_expand(const float* __restrict__ expand_w) {
    int chunk = blockIdx.x, b = blockIdx.y;
    int n0 = chunk * 8;
    __shared__ float s[8*392];
    __shared__ float w[192];
    __shared__ float red[6][256];
    int t = threadIdx.x;
    for (int i = t; i < 8*392; i += 256)
        s[i] = g_attn[((size_t)b*3136 + n0)*392 + i];
    if (t < 192) w[t] = expand_w[t];
    __syncthreads();
    if (t < 64) {
        int n = t >> 3, h = t & 7;
        float* p = s + n*392 + h*49;
        float mx = -1e30f;
        for (int i = 0; i < 49; i++) mx = fmaxf(mx, p[i]);
        float sum = 0.f;
        for (int i = 0; i < 49; i++) { float e = __expf(p[i] - mx); p[i] = e; sum += e; }
        float inv = 1.f / sum;
        for (int i = 0; i < 49; i++) p[i] *= inv;
    }
    __syncthreads();
    float s0 = 0.f, s1 = 0.f, s2 = 0.f, q0 = 0.f, q1 = 0.f, q2 = 0.f;
    for (int idx = t; idx < 8*1176; idx += 256) {
        int n = idx / 1176, r = idx - n*1176;
        int c = r / 49, m = r - c*49;
        const float* sp = s + n*392 + m;
        const float* wp = w + c*8;
        float v = 0.f;
        #pragma unroll
        for (int h = 0; h < 8; h++) v += sp[h*49] * wp[h];
        g_hid1[(((size_t)b*3136 + n0 + n)*24 + c)*49 + m] = v;
        if (c < 8)       { s0 += v; q0 += v*v; }
        else if (c < 16) { s1 += v; q1 += v*v; }
        else             { s2 += v; q2 += v*v; }
    }
    red[0][t] = s0; red[1][t] = s1; red[2][t] = s2;
    red[3][t] = q0; red[4][t] = q1; red[5][t] = q2;
    __syncthreads();
    for (int st = 128; st; st >>= 1) {
        if (t < st)
            #pragma unroll
            for (int g = 0; g < 6; g++) red[g][t] += red[g][t+st];
        __syncthreads();
    }
    if (t < 3) {
        g_part1[((b*3 + t)*392 + chunk)*2]     = red[t][0];
        g_part1[((b*3 + t)*392 + chunk)*2 + 1] = red[t+3][0];
    }
}

// ---------------- stats finalize ----------------
__global__ void k_stats_final(const float* __restrict__ gs, const float* __restrict__ gb,
                              float* __restrict__ ab, const float* __restrict__ part,
                              int G, int npart) {
    int b = blockIdx.x / G, g = blockIdx.x % G;
    const float* p = part + (size_t)(b*G + g)*npart*2;
    float sm = 0.f, sq = 0.f;
    for (int i = threadIdx.x; i < npart; i += 256) { sm += p[2*i]; sq += p[2*i+1]; }
    __shared__ float rs[256], rq[256];
    __shared__ float mean_s, rstd_s;
    int t = threadIdx.x;
    rs[t] = sm; rq[t] = sq;
    __syncthreads();
    for (int st = 128; st; st >>= 1) {
        if (t < st) { rs[t] += rs[t+st]; rq[t] += rq[t+st]; }
        __syncthreads();
    }
    if (!t) {
        float cnt  = 8.f * 3136.f * 49.f;
        float mean = rs[0] / cnt;
        float var  = rq[0] / cnt - mean*mean;
        mean_s = mean;
        rstd_s = rsqrtf(var + 1e-5f);
    }
    __syncthreads();
    if (t < 8) {
        int c = g*8 + t;
        float A = rstd_s * gs[c];
        int CH = G*8;
        ab[(b*CH + c)*2]     = A;
        ab[(b*CH + c)*2 + 1] = gb[c] - mean_s*A;
    }
}

// ---------------- 8. depthwise 3x3 + norm1/swish fused + gn2 partials ----------------
__global__ void k_dw(const float* __restrict__ dw_w) {
    int nt = blockIdx.x, c = blockIdx.y, b = blockIdx.z;
    int n0 = nt * 16;
    __shared__ float s[18][51];
    __shared__ float w[9];
    __shared__ float red[2][256];
    float A  = g_ab1[(b*24 + c)*2];
    float Bc = g_ab1[(b*24 + c)*2 + 1];
    int t = threadIdx.x;
    if (t < 9) w[t] = dw_w[c*9 + t];
    for (int i = t; i < 18*51; i += 256) {
        int r = i / 51, cc = i % 51;
        int n = n0 - 1 + r, m = cc - 1;
        float v = 0.f;
        if (n >= 0 && n < 3136 && m >= 0 && m < 49) {
            float xx = g_hid1[(((size_t)b*3136 + n)*24 + c)*49 + m];
            v = swishf(A*xx + Bc);
        }
        s[r][cc] = v;
    }
    __syncthreads();
    float lsum = 0.f, lsq = 0.f;
    for (int o = t; o < 16*49; o += 256) {
        int ny = o / 49, m = o % 49;
        float acc = 0.f;
        #pragma unroll
        for (int dy = 0; dy < 3; dy++)
            #pragma unroll
            for (int dx = 0; dx < 3; dx++)
                acc += s[ny+dy][m+dx] * w[dy*3+dx];
        g_hid2[(((size_t)b*3136 + n0 + ny)*24 + c)*49 + m] = acc;
        lsum += acc; lsq += acc*acc;
    }
    red[0][t] = lsum; red[1][t] = lsq;
    __syncthreads();
    for (int st = 128; st; st >>= 1) {
        if (t < st) { red[0][t] += red[0][t+st]; red[1][t] += red[1][t+st]; }
        __syncthreads();
    }
    if (!t) {
        g_part2[((b*24 + c)*196 + nt)*2]     = red[0][0];
        g_part2[((b*24 + c)*196 + nt)*2 + 1] = red[1][0];
    }
}

// ---------------- 9. reduce 1x1 (24->8) + norm2/swish fused + gn3 partials ----------------
__global__ void k_reduce(const float* __restrict__ reduce_w) {
    int chunk = blockIdx.x, b = blockIdx.y;
    int n0 = chunk * 8;
    __shared__ float w[192];
    __shared__ float A2s[24], B2s[24];
    __shared__ float red[2][392];
    int t = threadIdx.x;
    if (t < 192) w[t] = reduce_w[t];
    if (t < 24) { A2s[t] = g_ab2[(b*24+t)*2]; B2s[t] = g_ab2[(b*24+t)*2+1]; }
    __syncthreads();
    int nl = t / 49, m = t % 49;
    int n = n0 + nl;
    float in[24];
    size_t ibase = (((size_t)b*3136 + n)*24)*49 + m;
    #pragma unroll
    for (int c = 0; c < 24; c++) {
        float xx = g_hid2[ibase + (size_t)c*49];
        in[c] = swishf(A2s[c]*xx + B2s[c]);
    }
    size_t obase = ((size_t)b*3136 + n)*392 + m;
    float lsum = 0.f, lsq = 0.f;
    #pragma unroll
    for (int h = 0; h < 8; h++) {
        float o = 0.f;
        #pragma unroll
        for (int c = 0; c < 24; c++) o += in[c] * w[h*24+c];
        g_attn[obase + h*49] = o;
        lsum += o; lsq += o*o;
    }
    red[0][t] = lsum; red[1][t] = lsq;
    __syncthreads();
    for (int st = 256; st; st >>= 1) {
        if (t < st && t + st < 392) { red[0][t] += red[0][t+st]; red[1][t] += red[1][t+st]; }
        __syncthreads();
    }
    if (!t) {
        g_part3[(b*392 + chunk)*2]     = red[0][0];
        g_part3[(b*392 + chunk)*2 + 1] = red[1][0];
    }
}

// ---------------- 10. GEMM2 (tf32x3): out = norm3(attn) . Wvp + proj_b ----------------
// block tile 128n x 64c, k over 392 (j); 8 warps, warp tile 16n x 64c
__global__ __launch_bounds__(256) void k_gemm2(const float* __restrict__ proj_b,
                                               float* __restrict__ out) {
    int b = blockIdx.z, nt0 = blockIdx.y*128, ct0 = blockIdx.x*64;
    __shared__ uint32_t Ah[16*PADA], Al[16*PADA], Bh[16*PADB], Bl[16*PADB];
    __shared__ float A3s[8], B3s[8];
    int t = threadIdx.x, w = t >> 5, lane = t & 31;
    if (t < 8) { A3s[t] = g_ab3[(b*8+t)*2]; B3s[t] = g_ab3[(b*8+t)*2+1]; }
    float acc[8][4];
    #pragma unroll
    for (int i = 0; i < 8; i++)
        #pragma unroll
        for (int k = 0; k < 4; k++) acc[i][k] = 0.f;
    const float* ap = g_attn + (size_t)b*3136*392;
    const float* wb = g_Wvp  + (size_t)b*392*512;
    __syncthreads();
    for (int k0 = 0; k0 < 400; k0 += 16) {
        // A: 128n x 16j -> As[kk][nn]; LDG: 16 lanes cover consecutive j
        #pragma unroll
        for (int r = 0; r < 8; r++) {
            int i = t + 256*r;
            int nn = i >> 4, kk = i & 15;
            int n = nt0 + nn, j = k0 + kk;
            float v = 0.f;
            if (n < 3136 && j < 392) {
                int h = j / 49;
                v = ap[(size_t)n*392 + j] * A3s[h] + B3s[h];
            }
            uint32_t hi = f2tf32(v);
            Ah[kk*PADA + nn] = hi;
            Al[kk*PADA + nn] = f2tf32(v - __uint_as_float(hi));
        }
        // B: 16j x 64c
        #pragma unroll
        for (int r = 0; r < 4; r++) {
            int i = t + 256*r;
            int kk = i >> 6, cc = i & 63;
            int j = k0 + kk;
            float v = (j < 392) ? wb[(size_t)j*512 + ct0 + cc] : 0.f;
            uint32_t hi = f2tf32(v);
            Bh[kk*PADB + cc] = hi;
            Bl[kk*PADB + cc] = f2tf32(v - __uint_as_float(hi));
        }
        __syncthreads();
        #pragma unroll
        for (int kc = 0; kc < 2; kc++) {
            int kb = kc*8;
            uint32_t ah[4], al[4];
            int row = w*16 + (lane >> 2), col = kb + (lane & 3);
            ah[0] = Ah[col*PADA + row];       al[0] = Al[col*PADA + row];
            ah[1] = Ah[col*PADA + row+8];     al[1] = Al[col*PADA + row+8];
            ah[2] = Ah[(col+4)*PADA + row];   al[2] = Al[(col+4)*PADA + row];
            ah[3] = Ah[(col+4)*PADA + row+8]; al[3] = Al[(col+4)*PADA + row+8];
            #pragma unroll
            for (int cu = 0; cu < 8; cu++) {
                uint32_t bh[2], bl[2];
                int jc = cu*8 + (lane >> 2), kr = kb + (lane & 3);
                bh[0] = Bh[kr*PADB + jc];     bl[0] = Bl[kr*PADB + jc];
                bh[1] = Bh[(kr+4)*PADB + jc]; bl[1] = Bl[(kr+4)*PADB + jc];
                mma_tf32(acc[cu], ah, bh);
                mma_tf32(acc[cu], ah, bl);
                mma_tf32(acc[cu], al, bh);
            }
        }
        __syncthreads();
    }
    int row = nt0 + w*16 + (lane >> 2);
    #pragma unroll
    for (int cu = 0; cu < 8; cu++) {
        int c0 = ct0 + cu*8 + 2*(lane & 3);
        #pragma unroll
        for (int half = 0; half < 2; half++) {
            int n = row + half*8;
            if (n >= 3136) continue;
            #pragma unroll
            for (int e = 0; e < 2; e++) {
                int c = c0 + e;
                out[((size_t)b*3136 + n)*512 + c] = acc[cu][half*2 + e] + proj_b[c];
            }
        }
    }
}

// ---------------- launcher ----------------
extern "C" void kernel_launch(void* const* d_in, const int* in_sizes, int n_in,
                              void* d_out, int out_size) {
    const float* x        = (const float*)d_in[0];
    const float* q_w      = (const float*)d_in[1];
    const float* down_w   = (const float*)d_in[2];
    const float* kv_w     = (const float*)d_in[3];
    const float* proj_w   = (const float*)d_in[4];
    const float* proj_b   = (const float*)d_in[5];
    const float* rel_bias = (const float*)d_in[6];
    const float* expand_w = (const float*)d_in[7];
    const float* gn1_s    = (const float*)d_in[8];
    const float* gn1_b    = (const float*)d_in[9];
    const float* dw_w     = (const float*)d_in[10];
    const float* gn2_s    = (const float*)d_in[11];
    const float* gn2_b    = (const float*)d_in[12];
    const float* reduce_w = (const float*)d_in[13];
    const float* gn3_s    = (const float*)d_in[14];
    const float* gn3_b    = (const float*)d_in[15];
    float* out = (float*)d_out;

    float *ab1, *ab2, *ab3, *p1, *p2, *p3;
    cudaGetSymbolAddress((void**)&ab1, g_ab1);
    cudaGetSymbolAddress((void**)&ab2, g_ab2);
    cudaGetSymbolAddress((void**)&ab3, g_ab3);
    cudaGetSymbolAddress((void**)&p1, g_part1);
    cudaGetSymbolAddress((void**)&p2, g_part2);
    cudaGetSymbolAddress((void**)&p3, g_part3);

    k_down<<<BB*CCH, 256>>>(x, down_w);
    k_kv  <<<dim3(4, 7, BB), 256>>>(kv_w);
    k_wqk <<<dim3(2, 8, BB), 256>>>(q_w);
    k_wvp <<<dim3(7, 8, BB), 256>>>(proj_w);
    k_gemm1<<<dim3(7, 25, BB), 256>>>(x, rel_bias);
    k_sm_expand<<<dim3(392, BB), 256>>>(expand_w);
    k_stats_final<<<BB*3, 256>>>(gn1_s, gn1_b, ab1, p1, 3, 392);
    k_dw<<<dim3(196, 24, BB), 256>>>(dw_w);
    k_stats_final<<<BB*3, 256>>>(gn2_s, gn2_b, ab2, p2, 3, 1568);
    k_reduce<<<dim3(392, BB), 392>>>(reduce_w);
    k_stats_final<<<BB, 256>>>(gn3_s, gn3_b, ab3, p3, 1, 392);
    k_gemm2<<<dim3(8, 25, BB), 256>>>(proj_b, out);
}

// round 5
// speedup vs baseline: 1.7132x; 1.2276x over previous
#include <cuda_runtime.h>
#include <cuda_bf16.h>
#include <math.h>
#include <stdint.h>

#define BB    16
#define CCH   512
#define NN    3136
#define NKK   49
#define HEADS 8
#define JJ    392
#define HIDC  24
#define SCALE 0.125f

// ---------------- device scratch ----------------
__device__ float g_kvx[BB*NKK*CCH];
__device__ float g_kv [BB*NKK*1024];
__device__ float g_Wqk[BB*CCH*JJ];
__device__ float g_Wvp[BB*JJ*CCH];
__device__ __nv_bfloat16 g_xTh[(size_t)BB*NN*CCH];
__device__ __nv_bfloat16 g_xTl[(size_t)BB*NN*CCH];
__device__ __nv_bfloat16 g_wqh[BB*JJ*CCH];
__device__ __nv_bfloat16 g_wql[BB*JJ*CCH];
__device__ __nv_bfloat16 g_wvh[BB*CCH*JJ];
__device__ __nv_bfloat16 g_wvl[BB*CCH*JJ];
__device__ float g_attn[(size_t)BB*NN*JJ];
__device__ __nv_bfloat16 g_ath[(size_t)BB*NN*JJ];
__device__ __nv_bfloat16 g_atl[(size_t)BB*NN*JJ];
__device__ float g_part1[BB*3*392*2];
__device__ float g_part2[BB*3*196*2];
__device__ float g_part3[BB*196*2];
__device__ float g_ab1[BB*HIDC*2];
__device__ float g_ab2[BB*HIDC*2];
__device__ float g_ab3[BB*HEADS*2];
__device__ float g_bias2[BB*CCH];

__device__ __forceinline__ float swishf(float x) { return x / (1.f + __expf(-x)); }

__device__ __forceinline__ void bsplit(float v, __nv_bfloat16& h, __nv_bfloat16& l) {
    h = __float2bfloat16(v);
    l = __float2bfloat16(v - __bfloat162float(h));
}

__device__ __forceinline__ uint32_t smem_u32(const void* p) {
    uint32_t a;
    asm("{ .reg .u64 t; cvta.to.shared.u64 t, %1; cvt.u32.u64 %0, t; }" : "=r"(a) : "l"(p));
    return a;
}
__device__ __forceinline__ void ldm_x4(uint32_t* r, uint32_t addr) {
    asm volatile("ldmatrix.sync.aligned.m8n8.x4.shared.b16 {%0,%1,%2,%3}, [%4];"
        : "=r"(r[0]), "=r"(r[1]), "=r"(r[2]), "=r"(r[3]) : "r"(addr));
}
__device__ __forceinline__ void ldm_x2(uint32_t* r, uint32_t addr) {
    asm volatile("ldmatrix.sync.aligned.m8n8.x2.shared.b16 {%0,%1}, [%2];"
        : "=r"(r[0]), "=r"(r[1]) : "r"(addr));
}
__device__ __forceinline__ void mma_bf16(float* c, const uint32_t* a, const uint32_t* b) {
    asm volatile(
        "mma.sync.aligned.m16n8k16.row.col.f32.bf16.bf16.f32 "
        "{%0,%1,%2,%3}, {%4,%5,%6,%7}, {%8,%9}, {%0,%1,%2,%3};"
        : "+f"(c[0]), "+f"(c[1]), "+f"(c[2]), "+f"(c[3])
        : "r"(a[0]), "r"(a[1]), "r"(a[2]), "r"(a[3]), "r"(b[0]), "r"(b[1]));
}
__device__ __forceinline__ void cpa16(uint32_t dst, const void* src, bool v) {
    int sz = v ? 16 : 0;
    asm volatile("cp.async.cg.shared.global [%0], [%1], 16, %2;"
        :: "r"(dst), "l"(src), "r"(sz) : "memory");
}
__device__ __forceinline__ void cp_commit() {
    asm volatile("cp.async.commit_group;" ::: "memory");
}
__device__ __forceinline__ void cp_wait1() {
    asm volatile("cp.async.wait_group 1;" ::: "memory");
}
__device__ __forceinline__ void cp_wait0() {
    asm volatile("cp.async.wait_group 0;" ::: "memory");
}

// ---------------- 1. depthwise 8x8/8 downsample ----------------
__global__ void k_down(const float* __restrict__ x, const float* __restrict__ down_w) {
    int bc = blockIdx.x, c = bc & 511, b = bc >> 9;
    __shared__ float plane[3136];
    __shared__ float w[64];
    const float* xp = x + (size_t)bc * 3136;
    for (int i = threadIdx.x; i < 3136; i += 256) plane[i] = xp[i];
    if (threadIdx.x < 64) w[threadIdx.x] = down_w[c*64 + threadIdx.x];
    __syncthreads();
    if (threadIdx.x < 49) {
        int my = threadIdx.x / 7, mx = threadIdx.x % 7;
        float s = 0.f;
        #pragma unroll
        for (int i = 0; i < 8; i++)
            #pragma unroll
            for (int j = 0; j < 8; j++)
                s += plane[(my*8+i)*56 + mx*8 + j] * w[i*8+j];
        g_kvx[(b*49 + threadIdx.x)*512 + c] = s;
    }
}

// ---------------- 2. kv = kvx @ kv_w ----------------
__global__ void k_kv(const float* __restrict__ kv_w) {
    int b = blockIdx.z, m0 = blockIdx.y * 7, oc = blockIdx.x;
    __shared__ float a[7][512];
    for (int i = threadIdx.x; i < 7*512; i += 256)
        a[i >> 9][i & 511] = g_kvx[(b*49 + m0 + (i >> 9))*512 + (i & 511)];
    __syncthreads();
    int o = oc*256 + threadIdx.x;
    float acc[7] = {0,0,0,0,0,0,0};
    for (int c = 0; c < 512; c++) {
        float w = kv_w[c*1024 + o];
        #pragma unroll
        for (int mm = 0; mm < 7; mm++) acc[mm] += a[mm][c] * w;
    }
    #pragma unroll
    for (int mm = 0; mm < 7; mm++)
        g_kv[(b*49 + m0 + mm)*1024 + o] = acc[mm];
}

// ---------------- 3. Wqk ----------------
__global__ void k_wqk(const float* __restrict__ q_w) {
    int b = blockIdx.z, h = blockIdx.y, half = blockIdx.x;
    __shared__ float ks[49][64];
    for (int i = threadIdx.x; i < 49*64; i += 256)
        ks[i >> 6][i & 63] = g_kv[(b*49 + (i >> 6))*1024 + h*64 + (i & 63)];
    __syncthreads();
    int cin = half*256 + threadIdx.x;
    const float* qr = q_w + cin*512 + h*64;
    for (int mc = 0; mc < 49; mc += 7) {
        float acc[7] = {0,0,0,0,0,0,0};
        for (int d = 0; d < 64; d++) {
            float qd = qr[d];
            #pragma unroll
            for (int mm = 0; mm < 7; mm++) acc[mm] += qd * ks[mc+mm][d];
        }
        #pragma unroll
        for (int mm = 0; mm < 7; mm++)
            g_Wqk[(b*512 + cin)*392 + h*49 + mc + mm] = acc[mm] * SCALE;
    }
}

// ---------------- 4. Wvp ----------------
__global__ void k_wvp(const float* __restrict__ proj_w) {
    int b = blockIdx.z, h = blockIdx.y, mc = blockIdx.x * 7;
    __shared__ float vs[7][64];
    for (int i = threadIdx.x; i < 7*64; i += 256)
        vs[i >> 6][i & 63] = g_kv[(b*49 + mc + (i >> 6))*1024 + 512 + h*64 + (i & 63)];
    __syncthreads();
    int t = threadIdx.x;
    float acc[7][2] = {{0}};
    for (int d = 0; d < 64; d++) {
        float w0 = proj_w[(h*64+d)*512 + t];
        float w1 = proj_w[(h*64+d)*512 + 256 + t];
        #pragma unroll
        for (int mm = 0; mm < 7; mm++) {
            float vv = vs[mm][d];
            acc[mm][0] += vv * w0;
            acc[mm][1] += vv * w1;
        }
    }
    #pragma unroll
    for (int mm = 0; mm < 7; mm++) {
        int j = h*49 + mc + mm;
        g_Wvp[(b*392 + j)*512 + t]       = acc[mm][0];
        g_Wvp[(b*392 + j)*512 + 256 + t] = acc[mm][1];
    }
}

// ---------------- 4b. transpose+split x ----------------
__global__ void k_xsplit(const float* __restrict__ x) {
    int tn = blockIdx.x, tc = blockIdx.y, b = blockIdx.z;
    __shared__ float tile[32][33];
    int a = threadIdx.x >> 5, q = threadIdx.x & 31;
    #pragma unroll
    for (int r = 0; r < 4; r++) {
        int cc = tc*32 + a + r*8, nn = tn*32 + q;
        tile[a + r*8][q] = x[((size_t)b*512 + cc)*3136 + nn];
    }
    __syncthreads();
    #pragma unroll
    for (int r = 0; r < 4; r++) {
        int nn = tn*32 + a + r*8, cc = tc*32 + q;
        float v = tile[q][a + r*8];
        __nv_bfloat16 h, l; bsplit(v, h, l);
        size_t o = ((size_t)b*3136 + nn)*512 + cc;
        g_xTh[o] = h; g_xTl[o] = l;
    }
}

// ---------------- 4c. transpose+split Wqk ----------------
__global__ void k_bsplit(void) {
    int tj = blockIdx.x, tc = blockIdx.y, b = blockIdx.z;
    __shared__ float tile[32][33];
    int a = threadIdx.x >> 5, q = threadIdx.x & 31;
    #pragma unroll
    for (int r = 0; r < 4; r++) {
        int cc = tc*32 + a + r*8, jj = tj*32 + q;
        tile[a + r*8][q] = (jj < 392) ? g_Wqk[((size_t)b*512 + cc)*392 + jj] : 0.f;
    }
    __syncthreads();
    #pragma unroll
    for (int r = 0; r < 4; r++) {
        int jj = tj*32 + a + r*8, cc = tc*32 + q;
        if (jj < 392) {
            float v = tile[q][a + r*8];
            __nv_bfloat16 h, l; bsplit(v, h, l);
            size_t o = ((size_t)b*392 + jj)*512 + cc;
            g_wqh[o] = h; g_wql[o] = l;
        }
    }
}

// ---------------- 4d. transpose+scale+split Wvp ----------------
__global__ void k_wvpsplit(void) {
    int tj = blockIdx.x, tc = blockIdx.y, b = blockIdx.z;
    __shared__ float tile[32][33];
    int a = threadIdx.x >> 5, q = threadIdx.x & 31;
    #pragma unroll
    for (int r = 0; r < 4; r++) {
        int jj = tj*32 + a + r*8, cc = tc*32 + q;
        float v = 0.f;
        if (jj < 392) v = g_Wvp[((size_t)b*392 + jj)*512 + cc] * g_ab3[(b*8 + jj/49)*2];
        tile[a + r*8][q] = v;
    }
    __syncthreads();
    #pragma unroll
    for (int r = 0; r < 4; r++) {
        int cc = tc*32 + a + r*8, jj = tj*32 + q;
        if (jj < 392) {
            float v = tile[q][a + r*8];
            __nv_bfloat16 h, l; bsplit(v, h, l);
            size_t o = ((size_t)b*512 + cc)*392 + jj;
            g_wvh[o] = h; g_wvl[o] = l;
        }
    }
}

// ---------------- 4e. bias2 ----------------
__global__ void k_wvpbias(const float* __restrict__ proj_b) {
    int b = blockIdx.x, c = threadIdx.x;
    float acc = 0.f;
    for (int j = 0; j < 392; j++)
        acc += g_ab3[(b*8 + j/49)*2 + 1] * g_Wvp[((size_t)b*392 + j)*512 + c];
    g_bias2[b*512 + c] = acc + proj_b[c];
}

// ---------------- 5. GEMM1 (bf16x3 mma.sync): attn = xT . Wqk^T + rel_bias ----------------
// block 128n x 112j, warps 4n x 2j (warp tile 32n x 56j), k-tile 32, double-buffered cp.async
#define G1_BUF 19200   // bf16 elements per buffer
#define G1_AH 0
#define G1_AL 5120
#define G1_BH 10240
#define G1_BL 14720
#define G1_SMEM (G1_BUF*2*2)
__device__ __forceinline__ void g1_load(uint32_t sb, int b, int nt0, int jt0,
                                        int kt, int p, int t,
                                        const __nv_bfloat16* xh, const __nv_bfloat16* xl,
                                        const __nv_bfloat16* wh, const __nv_bfloat16* wl) {
    int k0 = kt*32;
    uint32_t base = sb + (uint32_t)p*G1_BUF*2;
    #pragma unroll
    for (int rr = 0; rr < 2; rr++) {
        int idx = t + rr*256;
        int row = idx >> 2, q = idx & 3;
        int n = nt0 + row;
        bool v = n < 3136;
        size_t e = ((size_t)b*3136 + (v ? n : 0))*512 + k0 + q*8;
        uint32_t doff = (uint32_t)(row*40 + q*8)*2;
        cpa16(base + G1_AH*2 + doff, xh + e, v);
        cpa16(base + G1_AL*2 + doff, xl + e, v);
    }
    #pragma unroll
    for (int rr = 0; rr < 2; rr++) {
        int idx = t + rr*256;
        if (idx < 448) {
            int row = idx >> 2, q = idx & 3;
            int j = jt0 + row;
            bool v = j < 392;
            size_t e = ((size_t)b*392 + (v ? j : 0))*512 + k0 + q*8;
            uint32_t doff = (uint32_t)(row*40 + q*8)*2;
            cpa16(base + G1_BH*2 + doff, wh + e, v);
            cpa16(base + G1_BL*2 + doff, wl + e, v);
        }
    }
}

__global__ __launch_bounds__(256) void k_gemm1_mma(const float* __restrict__ rel_bias) {
    extern __shared__ __nv_bfloat16 dsm[];
    uint32_t sb = smem_u32(dsm);
    int b = blockIdx.z, nt0 = blockIdx.y*128, jt0 = blockIdx.x*112;
    int t = threadIdx.x, w = t >> 5, lane = t & 31;
    int wn = (w & 3)*32, wj = (w >> 2)*56;
    float acc[2][7][4];
    #pragma unroll
    for (int i = 0; i < 2; i++)
        #pragma unroll
        for (int j = 0; j < 7; j++)
            #pragma unroll
            for (int k = 0; k < 4; k++) acc[i][j][k] = 0.f;

    g1_load(sb, b, nt0, jt0, 0, 0, t, g_xTh, g_xTl, g_wqh, g_wql);
    cp_commit();
    for (int kt = 0; kt < 16; kt++) {
        if (kt < 15) {
            g1_load(sb, b, nt0, jt0, kt+1, (kt+1) & 1, t, g_xTh, g_xTl, g_wqh, g_wql);
            cp_commit();
            cp_wait1();
        } else cp_wait0();
        __syncthreads();
        uint32_t base = sb + (uint32_t)(kt & 1)*G1_BUF*2;
        #pragma unroll
        for (int kk = 0; kk < 2; kk++) {
            int kb = kk*16;
            uint32_t ah[2][4], al[2][4];
            #pragma unroll
            for (int mt = 0; mt < 2; mt++) {
                int row = wn + mt*16 + (lane & 15);
                int col = kb + ((lane & 16) ? 8 : 0);
                uint32_t off = (uint32_t)(row*40 + col)*2;
                ldm_x4(ah[mt], base + G1_AH*2 + off);
                ldm_x4(al[mt], base + G1_AL*2 + off);
            }
            uint32_t bh[7][2], bl[7][2];
            #pragma unroll
            for (int p = 0; p < 3; p++) {
                int jrow = wj + p*16 + (lane & 7) + ((lane & 16) ? 8 : 0);
                int col = kb + ((lane & 8) ? 8 : 0);
                uint32_t off = (uint32_t)(jrow*40 + col)*2;
                uint32_t r4[4];
                ldm_x4(r4, base + G1_BH*2 + off);
                bh[2*p][0]=r4[0]; bh[2*p][1]=r4[1]; bh[2*p+1][0]=r4[2]; bh[2*p+1][1]=r4[3];
                ldm_x4(r4, base + G1_BL*2 + off);
                bl[2*p][0]=r4[0]; bl[2*p][1]=r4[1]; bl[2*p+1][0]=r4[2]; bl[2*p+1][1]=r4[3];
            }
            {
                int jrow = wj + 48 + (lane & 7);
                int col = kb + ((lane & 8) ? 8 : 0);
                uint32_t off = (uint32_t)(jrow*40 + col)*2;
                ldm_x2(bh[6], base + G1_BH*2 + off);
                ldm_x2(bl[6], base + G1_BL*2 + off);
            }
            #pragma unroll
            for (int mt = 0; mt < 2; mt++)
                #pragma unroll
                for (int jt = 0; jt < 7; jt++) {
                    mma_bf16(acc[mt][jt], ah[mt], bh[jt]);
                    mma_bf16(acc[mt][jt], al[mt], bh[jt]);
                    mma_bf16(acc[mt][jt], ah[mt], bl[jt]);
                }
        }
        __syncthreads();
    }
    int nrow = nt0 + wn + (lane >> 2);
    #pragma unroll
    for (int mt = 0; mt < 2; mt++) {
        #pragma unroll
        for (int jt = 0; jt < 7; jt++) {
            int j0 = jt0 + wj + jt*8 + ((lane & 3) << 1);
            if (j0 < 392) {
                int m0 = j0 - (j0/49)*49;
                int m1 = (j0+1) - ((j0+1)/49)*49;
                #pragma unroll
                for (int half = 0; half < 2; half++) {
                    int n = nrow + mt*16 + half*8;
                    if (n < 3136) {
                        size_t o = ((size_t)b*3136 + n)*392 + j0;
                        g_attn[o]   = acc[mt][jt][half*2]   + rel_bias[(size_t)n*49 + m0];
                        g_attn[o+1] = acc[mt][jt][half*2+1] + rel_bias[(size_t)n*49 + m1];
                    }
                }
            }
        }
    }
}

// ---------------- 6. pass A: softmax (in place) + gn1 partials ----------------
__global__ __launch_bounds__(256) void k_softmax_gn1(const float* __restrict__ expand_w) {
    int chunk = blockIdx.x, b = blockIdx.y;
    int n0 = chunk * 8;
    __shared__ float s[8*392];
    __shared__ float w[192];
    __shared__ float red[6][256];
    int t = threadIdx.x;
    for (int i = t; i < 8*392; i += 256)
        s[i] = g_attn[((size_t)b*3136 + n0)*392 + i];
    if (t < 192) w[t] = expand_w[t];
    __syncthreads();
    if (t < 64) {
        int n = t >> 3, h = t & 7;
        float* p = s + n*392 + h*49;
        float mx = -1e30f;
        for (int i = 0; i < 49; i++) mx = fmaxf(mx, p[i]);
        float sum = 0.f;
        for (int i = 0; i < 49; i++) { float e = __expf(p[i] - mx); p[i] = e; sum += e; }
        float inv = 1.f / sum;
        for (int i = 0; i < 49; i++) p[i] *= inv;
    }
    __syncthreads();
    for (int i = t; i < 8*392; i += 256)
        g_attn[((size_t)b*3136 + n0)*392 + i] = s[i];
    float s0=0.f,s1=0.f,s2=0.f,q0=0.f,q1=0.f,q2=0.f;
    for (int idx = t; idx < 8*1176; idx += 256) {
        int n = idx / 1176, r = idx - n*1176;
        int c = r / 49, m = r - c*49;
        const float* sp = s + n*392 + m;
        const float* wp = w + c*8;
        float v = 0.f;
        #pragma unroll
        for (int h = 0; h < 8; h++) v += sp[h*49] * wp[h];
        if (c < 8)       { s0 += v; q0 += v*v; }
        else if (c < 16) { s1 += v; q1 += v*v; }
        else             { s2 += v; q2 += v*v; }
    }
    red[0][t]=s0; red[1][t]=s1; red[2][t]=s2; red[3][t]=q0; red[4][t]=q1; red[5][t]=q2;
    __syncthreads();
    for (int st = 128; st; st >>= 1) {
        if (t < st)
            #pragma unroll
            for (int g = 0; g < 6; g++) red[g][t] += red[g][t+st];
        __syncthreads();
    }
    if (t < 3) {
        g_part1[((b*3 + t)*392 + chunk)*2]     = red[t][0];
        g_part1[((b*3 + t)*392 + chunk)*2 + 1] = red[t+3][0];
    }
}

// ---------------- stats finalize ----------------
__global__ void k_stats_final(const float* __restrict__ gs, const float* __restrict__ gb,
                              float* __restrict__ ab, const float* __restrict__ part,
                              int G, int npart) {
    int b = blockIdx.x / G, g = blockIdx.x % G;
    const float* p = part + (size_t)(b*G + g)*npart*2;
    float sm = 0.f, sq = 0.f;
    for (int i = threadIdx.x; i < npart; i += 256) { sm += p[2*i]; sq += p[2*i+1]; }
    __shared__ float rs[256], rq[256];
    __shared__ float mean_s, rstd_s;
    int t = threadIdx.x;
    rs[t] = sm; rq[t] = sq;
    __syncthreads();
    for (int st = 128; st; st >>= 1) {
        if (t < st) { rs[t] += rs[t+st]; rq[t] += rq[t+st]; }
        __syncthreads();
    }
    if (!t) {
        float cnt  = 8.f * 3136.f * 49.f;
        float mean = rs[0] / cnt;
        float var  = rq[0] / cnt - mean*mean;
        mean_s = mean;
        rstd_s = rsqrtf(var + 1e-5f);
    }
    __syncthreads();
    if (t < 8) {
        int c = g*8 + t;
        float A = rstd_s * gs[c];
        int CH = G*8;
        ab[(b*CH + c)*2]     = A;
        ab[(b*CH + c)*2 + 1] = gb[c] - mean_s*A;
    }
}

// ---------------- 7. pass B: recompute expand+norm1+swish, dw conv -> gn2 partials ----------------
__global__ __launch_bounds__(256) void k_dw_gn2(const float* __restrict__ dw_w,
                                                const float* __restrict__ expand_w) {
    int nt = blockIdx.x, b = blockIdx.y;
    int n0 = nt * 16;
    __shared__ float at[18][392];
    __shared__ float hid[18][51];
    __shared__ float ew[192];
    __shared__ float red[6][256];
    int t = threadIdx.x;
    if (t < 192) ew[t] = expand_w[t];
    for (int i = t; i < 18*392; i += 256) {
        int r = i / 392, m = i - r*392;
        int n = n0 - 1 + r;
        at[r][m] = (n >= 0 && n < 3136) ? g_attn[((size_t)b*3136 + n)*392 + m] : 0.f;
    }
    __syncthreads();
    float gs[3] = {0,0,0}, gq[3] = {0,0,0};
    for (int c = 0; c < 24; c++) {
        float A1 = g_ab1[(b*24+c)*2], B1 = g_ab1[(b*24+c)*2+1];
        for (int i = t; i < 18*51; i += 256) {
            int r = i / 51, mm = i - r*51;
            int n = n0 - 1 + r;
            float v = 0.f;
            if (mm >= 1 && mm <= 49 && n >= 0 && n < 3136) {
                int m = mm - 1;
                const float* sp = &at[r][m];
                const float* wp = ew + c*8;
                float h = 0.f;
                #pragma unroll
                for (int hh = 0; hh < 8; hh++) h += sp[hh*49] * wp[hh];
                v = swishf(A1*h + B1);
            }
            hid[r][mm] = v;
        }
        __syncthreads();
        float lw[9];
        #pragma unroll
        for (int i = 0; i < 9; i++) lw[i] = dw_w[c*9 + i];
        int g = c >> 3;
        for (int o = t; o < 16*49; o += 256) {
            int ny = o / 49, m = o - ny*49;
            float a = 0.f;
            #pragma unroll
            for (int dy = 0; dy < 3; dy++)
                #pragma unroll
                for (int dx = 0; dx < 3; dx++)
                    a += hid[ny+dy][m+dx] * lw[dy*3+dx];
            gs[g] += a; gq[g] += a*a;
        }
        __syncthreads();
    }
    red[0][t]=gs[0]; red[1][t]=gs[1]; red[2][t]=gs[2];
    red[3][t]=gq[0]; red[4][t]=gq[1]; red[5][t]=gq[2];
    __syncthreads();
    for (int st = 128; st; st >>= 1) {
        if (t < st)
            #pragma unroll
            for (int g = 0; g < 6; g++) red[g][t] += red[g][t+st];
        __syncthreads();
    }
    if (t < 3) {
        g_part2[((b*3 + t)*196 + nt)*2]     = red[t][0];
        g_part2[((b*3 + t)*196 + nt)*2 + 1] = red[t+3][0];
    }
}

// ---------------- 8. pass C: recompute dw, norm2+swish, reduce -> split attnF + gn3 partials ----------------
#define PC_AT   0
#define PC_HID  7056
#define PC_DWS  7974
#define PC_RW   26790
#define PC_EW   26982
#define PC_AB   27174
#define PC_RED  27270
#define PC_SMEM ((27270 + 512)*4)
__global__ __launch_bounds__(256) void k_dla_out(const float* __restrict__ dw_w,
                                                 const float* __restrict__ expand_w,
                                                 const float* __restrict__ reduce_w) {
    extern __shared__ float sm[];
    float* at  = sm + PC_AT;
    float* hid = sm + PC_HID;
    float* dws = sm + PC_DWS;
    float* rw  = sm + PC_RW;
    float* ew  = sm + PC_EW;
    float* ab  = sm + PC_AB;
    float* red = sm + PC_RED;
    int nt = blockIdx.x, b = blockIdx.y;
    int n0 = nt * 16, t = threadIdx.x;
    if (t < 192) rw[t] = reduce_w[t];
    else if (t < 232) { /* idle */ }
    if (t >= 32 && t < 224) ew[t-32] = expand_w[t-32];
    if (t < 48) ab[t] = g_ab1[b*48 + t];
    else if (t < 96) ab[t] = g_ab2[b*48 + (t-48)];
    for (int i = t; i < 18*392; i += 256) {
        int r = i / 392, m = i - r*392;
        int n = n0 - 1 + r;
        at[r*392 + m] = (n >= 0 && n < 3136) ? g_attn[((size_t)b*3136 + n)*392 + m] : 0.f;
    }
    __syncthreads();
    for (int c = 0; c < 24; c++) {
        float A1 = ab[c*2], B1 = ab[c*2+1];
        for (int i = t; i < 18*51; i += 256) {
            int r = i / 51, mm = i - r*51;
            int n = n0 - 1 + r;
            float v = 0.f;
            if (mm >= 1 && mm <= 49 && n >= 0 && n < 3136) {
                int m = mm - 1;
                const float* sp = at + r*392 + m;
                const float* wp = ew + c*8;
                float h = 0.f;
                #pragma unroll
                for (int hh = 0; hh < 8; hh++) h += sp[hh*49] * wp[hh];
                v = swishf(A1*h + B1);
            }
            hid[r*51 + mm] = v;
        }
        __syncthreads();
        float lw[9];
        #pragma unroll
        for (int i = 0; i < 9; i++) lw[i] = dw_w[c*9 + i];
        for (int o = t; o < 16*49; o += 256) {
            int ny = o / 49, m = o - ny*49;
            float a = 0.f;
            #pragma unroll
            for (int dy = 0; dy < 3; dy++)
                #pragma unroll
                for (int dx = 0; dx < 3; dx++)
                    a += hid[(ny+dy)*51 + m+dx] * lw[dy*3+dx];
            dws[(ny*24 + c)*49 + m] = a;
        }
        __syncthreads();
    }
    float lsum = 0.f, lsq = 0.f;
    for (int o = t; o < 16*49; o += 256) {
        int ny = o / 49, m = o - ny*49;
        int n = n0 + ny;
        float in[24];
        #pragma unroll
        for (int c = 0; c < 24; c++)
            in[c] = swishf(ab[48 + c*2]*dws[(ny*24 + c)*49 + m] + ab[49 + c*2]);
        size_t ob = ((size_t)b*3136 + n)*392 + m;
        #pragma unroll
        for (int h = 0; h < 8; h++) {
            float r = 0.f;
            #pragma unroll
            for (int c = 0; c < 24; c++) r += in[c] * rw[h*24 + c];
            __nv_bfloat16 hh, ll; bsplit(r, hh, ll);
            g_ath[ob + h*49] = hh;
            g_atl[ob + h*49] = ll;
            lsum += r; lsq += r*r;
        }
    }
    red[t] = lsum; red[256 + t] = lsq;
    __syncthreads();
    for (int st = 128; st; st >>= 1) {
        if (t < st) { red[t] += red[t+st]; red[256+t] += red[256+t+st]; }
        __syncthreads();
    }
    if (!t) {
        g_part3[(b*196 + nt)*2]     = red[0];
        g_part3[(b*196 + nt)*2 + 1] = red[256];
    }
}

// ---------------- 9. GEMM2 (bf16x3 mma.sync): out = attnF . Wvp'^T + bias2 ----------------
// block 128n x 64c, warps 4n x 2c (warp 32n x 32c), k over j=392 (13 ktiles of 32)
#define G2_BUF 15360
#define G2_AH 0
#define G2_AL 5120
#define G2_BH 10240
#define G2_BL 12800
#define G2_SMEM (G2_BUF*2*2)
__device__ __forceinline__ void g2_load(uint32_t sb, int b, int nt0, int ct0,
                                        int kt, int p, int t) {
    int k0 = kt*32;
    uint32_t base = sb + (uint32_t)p*G2_BUF*2;
    #pragma unroll
    for (int rr = 0; rr < 2; rr++) {
        int idx = t + rr*256;
        int row = idx >> 2, q = idx & 3;
        int n = nt0 + row, j0 = k0 + q*8;
        bool v = (n < 3136) && (j0 < 392);
        size_t e = ((size_t)b*3136 + (n < 3136 ? n : 0))*392 + (j0 < 392 ? j0 : 0);
        uint32_t doff = (uint32_t)(row*40 + q*8)*2;
        cpa16(base + G2_AH*2 + doff, g_ath + e, v);
        cpa16(base + G2_AL*2 + doff, g_atl + e, v);
    }
    {
        int idx = t;
        int row = idx >> 2, q = idx & 3;
        int c = ct0 + row, j0 = k0 + q*8;
        bool v = j0 < 392;
        size_t e = ((size_t)b*512 + c)*392 + (v ? j0 : 0);
        uint32_t doff = (uint32_t)(row*40 + q*8)*2;
        cpa16(base + G2_BH*2 + doff, g_wvh + e, v);
        cpa16(base + G2_BL*2 + doff, g_wvl + e, v);
    }
}

__global__ __launch_bounds__(256) void k_gemm2_mma(float* __restrict__ out) {
    extern __shared__ __nv_bfloat16 dsm2[];
    uint32_t sb = smem_u32(dsm2);
    int b = blockIdx.z, nt0 = blockIdx.y*128, ct0 = blockIdx.x*64;
    int t = threadIdx.x, w = t >> 5, lane = t & 31;
    int wn = (w & 3)*32, wc = (w >> 2)*32;
    float acc[2][4][4];
    #pragma unroll
    for (int i = 0; i < 2; i++)
        #pragma unroll
        for (int j = 0; j < 4; j++)
            #pragma unroll
            for (int k = 0; k < 4; k++) acc[i][j][k] = 0.f;

    g2_load(sb, b, nt0, ct0, 0, 0, t);
    cp_commit();
    for (int kt = 0; kt < 13; kt++) {
        if (kt < 12) {
            g2_load(sb, b, nt0, ct0, kt+1, (kt+1) & 1, t);
            cp_commit();
            cp_wait1();
        } else cp_wait0();
        __syncthreads();
        uint32_t base = sb + (uint32_t)(kt & 1)*G2_BUF*2;
        #pragma unroll
        for (int kk = 0; kk < 2; kk++) {
            int kb = kk*16;
            uint32_t ah[2][4], al[2][4];
            #pragma unroll
            for (int mt = 0; mt < 2; mt++) {
                int row = wn + mt*16 + (lane & 15);
                int col = kb + ((lane & 16) ? 8 : 0);
                uint32_t off = (uint32_t)(row*40 + col)*2;
                ldm_x4(ah[mt], base + G2_AH*2 + off);
                ldm_x4(al[mt], base + G2_AL*2 + off);
            }
            uint32_t bh[4][2], bl[4][2];
            #pragma unroll
            for (int p = 0; p < 2; p++) {
                int crow = wc + p*16 + (lane & 7) + ((lane & 16) ? 8 : 0);
                int col = kb + ((lane & 8) ? 8 : 0);
                uint32_t off = (uint32_t)(crow*40 + col)*2;
                uint32_t r4[4];
                ldm_x4(r4, base + G2_BH*2 + off);
                bh[2*p][0]=r4[0]; bh[2*p][1]=r4[1]; bh[2*p+1][0]=r4[2]; bh[2*p+1][1]=r4[3];
                ldm_x4(r4, base + G2_BL*2 + off);
                bl[2*p][0]=r4[0]; bl[2*p][1]=r4[1]; bl[2*p+1][0]=r4[2]; bl[2*p+1][1]=r4[3];
            }
            #pragma unroll
            for (int mt = 0; mt < 2; mt++)
                #pragma unroll
                for (int ct = 0; ct < 4; ct++) {
                    mma_bf16(acc[mt][ct], ah[mt], bh[ct]);
                    mma_bf16(acc[mt][ct], al[mt], bh[ct]);
                    mma_bf16(acc[mt][ct], ah[mt], bl[ct]);
                }
        }
        __syncthreads();
    }
    int nrow = nt0 + wn + (lane >> 2);
    #pragma unroll
    for (int mt = 0; mt < 2; mt++) {
        #pragma unroll
        for (int ct = 0; ct < 4; ct++) {
            int c0 = ct0 + wc + ct*8 + ((lane & 3) << 1);
            float b0 = g_bias2[b*512 + c0];
            float b1 = g_bias2[b*512 + c0 + 1];
            #pragma unroll
            for (int half = 0; half < 2; half++) {
                int n = nrow + mt*16 + half*8;
                if (n < 3136) {
                    size_t o = ((size_t)b*3136 + n)*512 + c0;
                    *(float2*)&out[o] = make_float2(acc[mt][ct][half*2] + b0,
                                                    acc[mt][ct][half*2+1] + b1);
                }
            }
        }
    }
}

// ---------------- launcher ----------------
extern "C" void kernel_launch(void* const* d_in, const int* in_sizes, int n_in,
                              void* d_out, int out_size) {
    const float* x        = (const float*)d_in[0];
    const float* q_w      = (const float*)d_in[1];
    const float* down_w   = (const float*)d_in[2];
    const float* kv_w     = (const float*)d_in[3];
    const float* proj_w   = (const float*)d_in[4];
    const float* proj_b   = (const float*)d_in[5];
    const float* rel_bias = (const float*)d_in[6];
    const float* expand_w = (const float*)d_in[7];
    const float* gn1_s    = (const float*)d_in[8];
    const float* gn1_b    = (const float*)d_in[9];
    const float* dw_w     = (const float*)d_in[10];
    const float* gn2_s    = (const float*)d_in[11];
    const float* gn2_b    = (const float*)d_in[12];
    const float* reduce_w = (const float*)d_in[13];
    const float* gn3_s    = (const float*)d_in[14];
    const float* gn3_b    = (const float*)d_in[15];
    float* out = (float*)d_out;

    float *ab1, *ab2, *ab3, *p1, *p2, *p3;
    cudaGetSymbolAddress((void**)&ab1, g_ab1);
    cudaGetSymbolAddress((void**)&ab2, g_ab2);
    cudaGetSymbolAddress((void**)&ab3, g_ab3);
    cudaGetSymbolAddress((void**)&p1, g_part1);
    cudaGetSymbolAddress((void**)&p2, g_part2);
    cudaGetSymbolAddress((void**)&p3, g_part3);

    cudaFuncSetAttribute(k_gemm1_mma, cudaFuncAttributeMaxDynamicSharedMemorySize, G1_SMEM);
    cudaFuncSetAttribute(k_gemm2_mma, cudaFuncAttributeMaxDynamicSharedMemorySize, G2_SMEM);
    cudaFuncSetAttribute(k_dla_out,   cudaFuncAttributeMaxDynamicSharedMemorySize, PC_SMEM);

    k_xsplit<<<dim3(98, 16, BB), 256>>>(x);
    k_down<<<BB*CCH, 256>>>(x, down_w);
    k_kv  <<<dim3(4, 7, BB), 256>>>(kv_w);
    k_wqk <<<dim3(2, 8, BB), 256>>>(q_w);
    k_wvp <<<dim3(7, 8, BB), 256>>>(proj_w);
    k_bsplit<<<dim3(13, 16, BB), 256>>>();
    k_gemm1_mma<<<dim3(4, 25, BB), 256, G1_SMEM>>>(rel_bias);
    k_softmax_gn1<<<dim3(392, BB), 256>>>(expand_w);
    k_stats_final<<<BB*3, 256>>>(gn1_s, gn1_b, ab1, p1, 3, 392);
    k_dw_gn2<<<dim3(196, BB), 256>>>(dw_w, expand_w);
    k_stats_final<<<BB*3, 256>>>(gn2_s, gn2_b, ab2, p2, 3, 196);
    k_dla_out<<<dim3(196, BB), 256, PC_SMEM>>>(dw_w, expand_w, reduce_w);
    k_stats_final<<<BB, 256>>>(gn3_s, gn3_b, ab3, p3, 1, 196);
    k_wvpsplit<<<dim3(13, 16, BB), 256>>>();
    k_wvpbias<<<BB, 512>>>(proj_b);
    k_gemm2_mma<<<dim3(8, 25, BB), 256, G2_SMEM>>>(out);
}

// round 6
// speedup vs baseline: 1.8766x; 1.0954x over previous
#include <cuda_runtime.h>
#include <cuda_bf16.h>
#include <math.h>
#include <stdint.h>

#define BB    16
#define CCH   512
#define NN    3136
#define NKK   49
#define HEADS 8
#define JJ    392
#define HIDC  24
#define SCALE 0.125f

// ---------------- device scratch ----------------
__device__ float g_kvx[BB*NKK*CCH];
__device__ float g_kv [BB*NKK*1024];
__device__ float g_Wvp[BB*JJ*CCH];
__device__ __nv_bfloat16 g_xTh[(size_t)BB*NN*CCH];
__device__ __nv_bfloat16 g_xTl[(size_t)BB*NN*CCH];
__device__ __nv_bfloat16 g_wqh[BB*JJ*CCH];
__device__ __nv_bfloat16 g_wql[BB*JJ*CCH];
__device__ __nv_bfloat16 g_wvh[BB*CCH*JJ];
__device__ __nv_bfloat16 g_wvl[BB*CCH*JJ];
__device__ float g_attn[(size_t)BB*NN*JJ];
__device__ __nv_bfloat16 g_ath[(size_t)BB*NN*JJ];
__device__ __nv_bfloat16 g_atl[(size_t)BB*NN*JJ];
__device__ float g_part1[BB*3*392*2];
__device__ float g_part2[BB*3*196*2];
__device__ float g_part3[BB*392*2];
__device__ float g_ab1[BB*HIDC*2];
__device__ float g_ab2[BB*HIDC*2];
__device__ float g_ab3[BB*HEADS*2];
__device__ float g_bias2[BB*CCH];

__device__ __forceinline__ float swishf(float x) { return x / (1.f + __expf(-x)); }

__device__ __forceinline__ void bsplit(float v, __nv_bfloat16& h, __nv_bfloat16& l) {
    h = __float2bfloat16(v);
    l = __float2bfloat16(v - __bfloat162float(h));
}

__device__ __forceinline__ uint32_t smem_u32(const void* p) {
    uint32_t a;
    asm("{ .reg .u64 t; cvta.to.shared.u64 t, %1; cvt.u32.u64 %0, t; }" : "=r"(a) : "l"(p));
    return a;
}
__device__ __forceinline__ void ldm_x4(uint32_t* r, uint32_t addr) {
    asm volatile("ldmatrix.sync.aligned.m8n8.x4.shared.b16 {%0,%1,%2,%3}, [%4];"
        : "=r"(r[0]), "=r"(r[1]), "=r"(r[2]), "=r"(r[3]) : "r"(addr));
}
__device__ __forceinline__ void ldm_x2(uint32_t* r, uint32_t addr) {
    asm volatile("ldmatrix.sync.aligned.m8n8.x2.shared.b16 {%0,%1}, [%2];"
        : "=r"(r[0]), "=r"(r[1]) : "r"(addr));
}
__device__ __forceinline__ void mma_bf16(float* c, const uint32_t* a, const uint32_t* b) {
    asm volatile(
        "mma.sync.aligned.m16n8k16.row.col.f32.bf16.bf16.f32 "
        "{%0,%1,%2,%3}, {%4,%5,%6,%7}, {%8,%9}, {%0,%1,%2,%3};"
        : "+f"(c[0]), "+f"(c[1]), "+f"(c[2]), "+f"(c[3])
        : "r"(a[0]), "r"(a[1]), "r"(a[2]), "r"(a[3]), "r"(b[0]), "r"(b[1]));
}
__device__ __forceinline__ void cpa16(uint32_t dst, const void* src, bool v) {
    int sz = v ? 16 : 0;
    asm volatile("cp.async.cg.shared.global [%0], [%1], 16, %2;"
        :: "r"(dst), "l"(src), "r"(sz) : "memory");
}
__device__ __forceinline__ void cp_commit() {
    asm volatile("cp.async.commit_group;" ::: "memory");
}
__device__ __forceinline__ void cp_wait1() {
    asm volatile("cp.async.wait_group 1;" ::: "memory");
}
__device__ __forceinline__ void cp_wait0() {
    asm volatile("cp.async.wait_group 0;" ::: "memory");
}

// ---------------- 1. depthwise 8x8/8 downsample ----------------
__global__ void k_down(const float* __restrict__ x, const float* __restrict__ down_w) {
    int bc = blockIdx.x, c = bc & 511, b = bc >> 9;
    __shared__ float plane[3136];
    __shared__ float w[64];
    const float* xp = x + (size_t)bc * 3136;
    for (int i = threadIdx.x; i < 3136; i += 256) plane[i] = xp[i];
    if (threadIdx.x < 64) w[threadIdx.x] = down_w[c*64 + threadIdx.x];
    __syncthreads();
    if (threadIdx.x < 49) {
        int my = threadIdx.x / 7, mx = threadIdx.x % 7;
        float s = 0.f;
        #pragma unroll
        for (int i = 0; i < 8; i++)
            #pragma unroll
            for (int j = 0; j < 8; j++)
                s += plane[(my*8+i)*56 + mx*8 + j] * w[i*8+j];
        g_kvx[(b*49 + threadIdx.x)*512 + c] = s;
    }
}

// ---------------- 2. kv = kvx @ kv_w ----------------
__global__ void k_kv(const float* __restrict__ kv_w) {
    int b = blockIdx.z, m0 = blockIdx.y * 7, oc = blockIdx.x;
    __shared__ float a[7][512];
    for (int i = threadIdx.x; i < 7*512; i += 256)
        a[i >> 9][i & 511] = g_kvx[(b*49 + m0 + (i >> 9))*512 + (i & 511)];
    __syncthreads();
    int o = oc*256 + threadIdx.x;
    float acc[7] = {0,0,0,0,0,0,0};
    for (int c = 0; c < 512; c++) {
        float w = kv_w[c*1024 + o];
        #pragma unroll
        for (int mm = 0; mm < 7; mm++) acc[mm] += a[mm][c] * w;
    }
    #pragma unroll
    for (int mm = 0; mm < 7; mm++)
        g_kv[(b*49 + m0 + mm)*1024 + o] = acc[mm];
}

// ---------------- 3. Wqk fused compute + bf16 split: g_wqh/g_wql[(b,j,cin)] ----------------
__global__ __launch_bounds__(256) void k_wqk_split(const float* __restrict__ q_w) {
    int half = blockIdx.x, h = blockIdx.y, b = blockIdx.z;
    __shared__ float ks[49][64];
    for (int i = threadIdx.x; i < 49*64; i += 256)
        ks[i >> 6][i & 63] = g_kv[(b*49 + (i >> 6))*1024 + h*64 + (i & 63)];
    __syncthreads();
    int cin = half*256 + threadIdx.x;
    float acc[49];
    #pragma unroll
    for (int m = 0; m < 49; m++) acc[m] = 0.f;
    const float4* q4 = (const float4*)(q_w + (size_t)cin*512 + h*64);
    const float4* ks4 = (const float4*)&ks[0][0];
    for (int d4 = 0; d4 < 16; d4++) {
        float4 q = __ldg(q4 + d4);
        #pragma unroll
        for (int m = 0; m < 49; m++) {
            float4 k = ks4[m*16 + d4];
            acc[m] += q.x*k.x + q.y*k.y + q.z*k.z + q.w*k.w;
        }
    }
    size_t obase = ((size_t)b*392 + h*49)*512 + cin;
    #pragma unroll
    for (int m = 0; m < 49; m++) {
        float v = acc[m] * SCALE;
        __nv_bfloat16 hh, ll; bsplit(v, hh, ll);
        g_wqh[obase + (size_t)m*512] = hh;
        g_wql[obase + (size_t)m*512] = ll;
    }
}

// ---------------- 4. Wvp ----------------
__global__ void k_wvp(const float* __restrict__ proj_w) {
    int b = blockIdx.z, h = blockIdx.y, mc = blockIdx.x * 7;
    __shared__ float vs[7][64];
    for (int i = threadIdx.x; i < 7*64; i += 256)
        vs[i >> 6][i & 63] = g_kv[(b*49 + mc + (i >> 6))*1024 + 512 + h*64 + (i & 63)];
    __syncthreads();
    int t = threadIdx.x;
    float acc[7][2] = {{0}};
    for (int d = 0; d < 64; d++) {
        float w0 = proj_w[(h*64+d)*512 + t];
        float w1 = proj_w[(h*64+d)*512 + 256 + t];
        #pragma unroll
        for (int mm = 0; mm < 7; mm++) {
            float vv = vs[mm][d];
            acc[mm][0] += vv * w0;
            acc[mm][1] += vv * w1;
        }
    }
    #pragma unroll
    for (int mm = 0; mm < 7; mm++) {
        int j = h*49 + mc + mm;
        g_Wvp[(b*392 + j)*512 + t]       = acc[mm][0];
        g_Wvp[(b*392 + j)*512 + 256 + t] = acc[mm][1];
    }
}

// ---------------- 4b. transpose+split x ----------------
__global__ void k_xsplit(const float* __restrict__ x) {
    int tn = blockIdx.x, tc = blockIdx.y, b = blockIdx.z;
    __shared__ float tile[32][33];
    int a = threadIdx.x >> 5, q = threadIdx.x & 31;
    #pragma unroll
    for (int r = 0; r < 4; r++) {
        int cc = tc*32 + a + r*8, nn = tn*32 + q;
        tile[a + r*8][q] = x[((size_t)b*512 + cc)*3136 + nn];
    }
    __syncthreads();
    #pragma unroll
    for (int r = 0; r < 4; r++) {
        int nn = tn*32 + a + r*8, cc = tc*32 + q;
        float v = tile[q][a + r*8];
        __nv_bfloat16 h, l; bsplit(v, h, l);
        size_t o = ((size_t)b*3136 + nn)*512 + cc;
        g_xTh[o] = h; g_xTl[o] = l;
    }
}

// ---------------- 4d. transpose+scale+split Wvp ----------------
__global__ void k_wvpsplit(void) {
    int tj = blockIdx.x, tc = blockIdx.y, b = blockIdx.z;
    __shared__ float tile[32][33];
    int a = threadIdx.x >> 5, q = threadIdx.x & 31;
    #pragma unroll
    for (int r = 0; r < 4; r++) {
        int jj = tj*32 + a + r*8, cc = tc*32 + q;
        float v = 0.f;
        if (jj < 392) v = g_Wvp[((size_t)b*392 + jj)*512 + cc] * g_ab3[(b*8 + jj/49)*2];
        tile[a + r*8][q] = v;
    }
    __syncthreads();
    #pragma unroll
    for (int r = 0; r < 4; r++) {
        int cc = tc*32 + a + r*8, jj = tj*32 + q;
        if (jj < 392) {
            float v = tile[q][a + r*8];
            __nv_bfloat16 h, l; bsplit(v, h, l);
            size_t o = ((size_t)b*512 + cc)*392 + jj;
            g_wvh[o] = h; g_wvl[o] = l;
        }
    }
}

// ---------------- 4e. bias2 ----------------
__global__ void k_wvpbias(const float* __restrict__ proj_b) {
    int b = blockIdx.x, c = threadIdx.x;
    float acc = 0.f;
    for (int j = 0; j < 392; j++)
        acc += g_ab3[(b*8 + j/49)*2 + 1] * g_Wvp[((size_t)b*392 + j)*512 + c];
    g_bias2[b*512 + c] = acc + proj_b[c];
}

// ---------------- 5. GEMM1 (bf16x3 mma.sync) ----------------
#define G1_BUF 19200
#define G1_AH 0
#define G1_AL 5120
#define G1_BH 10240
#define G1_BL 14720
#define G1_SMEM (G1_BUF*2*2)
__device__ __forceinline__ void g1_load(uint32_t sb, int b, int nt0, int jt0,
                                        int kt, int p, int t,
                                        const __nv_bfloat16* xh, const __nv_bfloat16* xl,
                                        const __nv_bfloat16* wh, const __nv_bfloat16* wl) {
    int k0 = kt*32;
    uint32_t base = sb + (uint32_t)p*G1_BUF*2;
    #pragma unroll
    for (int rr = 0; rr < 2; rr++) {
        int idx = t + rr*256;
        int row = idx >> 2, q = idx & 3;
        int n = nt0 + row;
        bool v = n < 3136;
        size_t e = ((size_t)b*3136 + (v ? n : 0))*512 + k0 + q*8;
        uint32_t doff = (uint32_t)(row*40 + q*8)*2;
        cpa16(base + G1_AH*2 + doff, xh + e, v);
        cpa16(base + G1_AL*2 + doff, xl + e, v);
    }
    #pragma unroll
    for (int rr = 0; rr < 2; rr++) {
        int idx = t + rr*256;
        if (idx < 448) {
            int row = idx >> 2, q = idx & 3;
            int j = jt0 + row;
            bool v = j < 392;
            size_t e = ((size_t)b*392 + (v ? j : 0))*512 + k0 + q*8;
            uint32_t doff = (uint32_t)(row*40 + q*8)*2;
            cpa16(base + G1_BH*2 + doff, wh + e, v);
            cpa16(base + G1_BL*2 + doff, wl + e, v);
        }
    }
}

__global__ __launch_bounds__(256) void k_gemm1_mma(const float* __restrict__ rel_bias) {
    extern __shared__ __nv_bfloat16 dsm[];
    uint32_t sb = smem_u32(dsm);
    int b = blockIdx.z, nt0 = blockIdx.y*128, jt0 = blockIdx.x*112;
    int t = threadIdx.x, w = t >> 5, lane = t & 31;
    int wn = (w & 3)*32, wj = (w >> 2)*56;
    float acc[2][7][4];
    #pragma unroll
    for (int i = 0; i < 2; i++)
        #pragma unroll
        for (int j = 0; j < 7; j++)
            #pragma unroll
            for (int k = 0; k < 4; k++) acc[i][j][k] = 0.f;

    g1_load(sb, b, nt0, jt0, 0, 0, t, g_xTh, g_xTl, g_wqh, g_wql);
    cp_commit();
    for (int kt = 0; kt < 16; kt++) {
        if (kt < 15) {
            g1_load(sb, b, nt0, jt0, kt+1, (kt+1) & 1, t, g_xTh, g_xTl, g_wqh, g_wql);
            cp_commit();
            cp_wait1();
        } else cp_wait0();
        __syncthreads();
        uint32_t base = sb + (uint32_t)(kt & 1)*G1_BUF*2;
        #pragma unroll
        for (int kk = 0; kk < 2; kk++) {
            int kb = kk*16;
            uint32_t ah[2][4], al[2][4];
            #pragma unroll
            for (int mt = 0; mt < 2; mt++) {
                int row = wn + mt*16 + (lane & 15);
                int col = kb + ((lane & 16) ? 8 : 0);
                uint32_t off = (uint32_t)(row*40 + col)*2;
                ldm_x4(ah[mt], base + G1_AH*2 + off);
                ldm_x4(al[mt], base + G1_AL*2 + off);
            }
            uint32_t bh[7][2], bl[7][2];
            #pragma unroll
            for (int p = 0; p < 3; p++) {
                int jrow = wj + p*16 + (lane & 7) + ((lane & 16) ? 8 : 0);
                int col = kb + ((lane & 8) ? 8 : 0);
                uint32_t off = (uint32_t)(jrow*40 + col)*2;
                uint32_t r4[4];
                ldm_x4(r4, base + G1_BH*2 + off);
                bh[2*p][0]=r4[0]; bh[2*p][1]=r4[1]; bh[2*p+1][0]=r4[2]; bh[2*p+1][1]=r4[3];
                ldm_x4(r4, base + G1_BL*2 + off);
                bl[2*p][0]=r4[0]; bl[2*p][1]=r4[1]; bl[2*p+1][0]=r4[2]; bl[2*p+1][1]=r4[3];
            }
            {
                int jrow = wj + 48 + (lane & 7);
                int col = kb + ((lane & 8) ? 8 : 0);
                uint32_t off = (uint32_t)(jrow*40 + col)*2;
                ldm_x2(bh[6], base + G1_BH*2 + off);
                ldm_x2(bl[6], base + G1_BL*2 + off);
            }
            #pragma unroll
            for (int mt = 0; mt < 2; mt++)
                #pragma unroll
                for (int jt = 0; jt < 7; jt++) {
                    mma_bf16(acc[mt][jt], ah[mt], bh[jt]);
                    mma_bf16(acc[mt][jt], al[mt], bh[jt]);
                    mma_bf16(acc[mt][jt], ah[mt], bl[jt]);
                }
        }
        __syncthreads();
    }
    int nrow = nt0 + wn + (lane >> 2);
    #pragma unroll
    for (int mt = 0; mt < 2; mt++) {
        #pragma unroll
        for (int jt = 0; jt < 7; jt++) {
            int j0 = jt0 + wj + jt*8 + ((lane & 3) << 1);
            if (j0 < 392) {
                int m0 = j0 - (j0/49)*49;
                int m1 = (j0+1) - ((j0+1)/49)*49;
                #pragma unroll
                for (int half = 0; half < 2; half++) {
                    int n = nrow + mt*16 + half*8;
                    if (n < 3136) {
                        size_t o = ((size_t)b*3136 + n)*392 + j0;
                        g_attn[o]   = acc[mt][jt][half*2]   + rel_bias[(size_t)n*49 + m0];
                        g_attn[o+1] = acc[mt][jt][half*2+1] + rel_bias[(size_t)n*49 + m1];
                    }
                }
            }
        }
    }
}

// ---------------- 6. pass A: softmax (in place) + gn1 partials ----------------
__global__ __launch_bounds__(256) void k_softmax_gn1(const float* __restrict__ expand_w) {
    int chunk = blockIdx.x, b = blockIdx.y;
    int n0 = chunk * 8;
    __shared__ float s[8*392];
    __shared__ float w[192];
    __shared__ float red[6][256];
    int t = threadIdx.x;
    for (int i = t; i < 8*392; i += 256)
        s[i] = g_attn[((size_t)b*3136 + n0)*392 + i];
    if (t < 192) w[t] = expand_w[t];
    __syncthreads();
    if (t < 64) {
        int n = t >> 3, h = t & 7;
        float* p = s + n*392 + h*49;
        float mx = -1e30f;
        for (int i = 0; i < 49; i++) mx = fmaxf(mx, p[i]);
        float sum = 0.f;
        for (int i = 0; i < 49; i++) { float e = __expf(p[i] - mx); p[i] = e; sum += e; }
        float inv = 1.f / sum;
        for (int i = 0; i < 49; i++) p[i] *= inv;
    }
    __syncthreads();
    for (int i = t; i < 8*392; i += 256)
        g_attn[((size_t)b*3136 + n0)*392 + i] = s[i];
    float s0=0.f,s1=0.f,s2=0.f,q0=0.f,q1=0.f,q2=0.f;
    for (int idx = t; idx < 8*1176; idx += 256) {
        int n = idx / 1176, r = idx - n*1176;
        int c = r / 49, m = r - c*49;
        const float* sp = s + n*392 + m;
        const float* wp = w + c*8;
        float v = 0.f;
        #pragma unroll
        for (int h = 0; h < 8; h++) v += sp[h*49] * wp[h];
        if (c < 8)       { s0 += v; q0 += v*v; }
        else if (c < 16) { s1 += v; q1 += v*v; }
        else             { s2 += v; q2 += v*v; }
    }
    red[0][t]=s0; red[1][t]=s1; red[2][t]=s2; red[3][t]=q0; red[4][t]=q1; red[5][t]=q2;
    __syncthreads();
    for (int st = 128; st; st >>= 1) {
        if (t < st)
            #pragma unroll
            for (int g = 0; g < 6; g++) red[g][t] += red[g][t+st];
        __syncthreads();
    }
    if (t < 3) {
        g_part1[((b*3 + t)*392 + chunk)*2]     = red[t][0];
        g_part1[((b*3 + t)*392 + chunk)*2 + 1] = red[t+3][0];
    }
}

// ---------------- stats finalize ----------------
__global__ void k_stats_final(const float* __restrict__ gs, const float* __restrict__ gb,
                              float* __restrict__ ab, const float* __restrict__ part,
                              int G, int npart) {
    int b = blockIdx.x / G, g = blockIdx.x % G;
    const float* p = part + (size_t)(b*G + g)*npart*2;
    float sm = 0.f, sq = 0.f;
    for (int i = threadIdx.x; i < npart; i += 256) { sm += p[2*i]; sq += p[2*i+1]; }
    __shared__ float rs[256], rq[256];
    __shared__ float mean_s, rstd_s;
    int t = threadIdx.x;
    rs[t] = sm; rq[t] = sq;
    __syncthreads();
    for (int st = 128; st; st >>= 1) {
        if (t < st) { rs[t] += rs[t+st]; rq[t] += rq[t+st]; }
        __syncthreads();
    }
    if (!t) {
        float cnt  = 8.f * 3136.f * 49.f;
        float mean = rs[0] / cnt;
        float var  = rq[0] / cnt - mean*mean;
        mean_s = mean;
        rstd_s = rsqrtf(var + 1e-5f);
    }
    __syncthreads();
    if (t < 8) {
        int c = g*8 + t;
        float A = rstd_s * gs[c];
        int CH = G*8;
        ab[(b*CH + c)*2]     = A;
        ab[(b*CH + c)*2 + 1] = gb[c] - mean_s*A;
    }
}

// ---------------- 7. pass B: warp-parallel expand+dw -> gn2 partials ----------------
// block = (nt of 16 n, b). 8 warps; warp w owns channels {w, w+8, w+16}.
#define B_AT  0
#define B_HID 7056
#define B_EW  14416
#define B_AB  14608
#define B_RED 14656
#define B_TOT (14656 + 1536)
#define B_SMEM (B_TOT*4)
__global__ __launch_bounds__(256) void k_dw_gn2(const float* __restrict__ dw_w,
                                                const float* __restrict__ expand_w) {
    extern __shared__ float sm[];
    float* at  = sm + B_AT;
    float* ew  = sm + B_EW;
    float* ab  = sm + B_AB;
    float* red = sm + B_RED;
    int nt = blockIdx.x, b = blockIdx.y, t = threadIdx.x;
    int w = t >> 5, lane = t & 31;
    float* hid = sm + B_HID + w*920;
    int n0 = nt * 16;
    if (t < 192) ew[t] = expand_w[t];
    if (t >= 192 && t < 240) ab[t-192] = g_ab1[b*48 + (t-192)];
    for (int i = t; i < 18*392; i += 256) {
        int r = i / 392, m = i - r*392;
        int n = n0 - 1 + r;
        at[i] = (n >= 0 && n < 3136) ? g_attn[((size_t)b*3136 + n)*392 + m] : 0.f;
    }
    __syncthreads();
    float sk[3] = {0,0,0}, qk[3] = {0,0,0};
    #pragma unroll
    for (int k = 0; k < 3; k++) {
        int c = w + k*8;
        float A1 = ab[c*2], B1 = ab[c*2+1];
        const float* wp = ew + c*8;
        for (int i = lane; i < 918; i += 32) {
            int r = i / 51, mm = i - r*51;
            int n = n0 - 1 + r;
            float v = 0.f;
            if (mm >= 1 && mm <= 49 && n >= 0 && n < 3136) {
                const float* sp = at + r*392 + (mm - 1);
                float hsum = 0.f;
                #pragma unroll
                for (int hh = 0; hh < 8; hh++) hsum += sp[hh*49] * wp[hh];
                v = swishf(A1*hsum + B1);
            }
            hid[i] = v;
        }
        __syncwarp();
        float lw[9];
        #pragma unroll
        for (int i = 0; i < 9; i++) lw[i] = dw_w[c*9 + i];
        for (int o = lane; o < 784; o += 32) {
            int ny = o / 49, m = o - ny*49;
            float a = 0.f;
            #pragma unroll
            for (int dy = 0; dy < 3; dy++)
                #pragma unroll
                for (int dx = 0; dx < 3; dx++)
                    a += hid[(ny+dy)*51 + m+dx] * lw[dy*3+dx];
            sk[k] += a; qk[k] += a*a;
        }
        __syncwarp();
    }
    #pragma unroll
    for (int g = 0; g < 3; g++) { red[g*256 + t] = sk[g]; red[(3+g)*256 + t] = qk[g]; }
    __syncthreads();
    for (int st = 128; st; st >>= 1) {
        if (t < st)
            #pragma unroll
            for (int g = 0; g < 6; g++) red[g*256 + t] += red[g*256 + t + st];
        __syncthreads();
    }
    if (t < 3) {
        g_part2[((b*3 + t)*196 + nt)*2]     = red[t*256];
        g_part2[((b*3 + t)*196 + nt)*2 + 1] = red[(t+3)*256];
    }
}

// ---------------- 8. pass C: warp-parallel expand+dw+norm2+swish, reduce -> attnF + gn3 ----------------
// block = (nt of 8 n, b). 8 warps; warp w owns channels {w, w+8, w+16}.
#define C_AT  0
#define C_HID 3920
#define C_DWS 8016
#define C_EW  17424
#define C_RW  17616
#define C_AB  17808
#define C_RED 17904
#define C_TOT (17904 + 512)
#define C_SMEM (C_TOT*4)
__global__ __launch_bounds__(256) void k_dla_out(const float* __restrict__ dw_w,
                                                 const float* __restrict__ expand_w,
                                                 const float* __restrict__ reduce_w) {
    extern __shared__ float sm[];
    float* at  = sm + C_AT;
    float* dws = sm + C_DWS;
    float* ew  = sm + C_EW;
    float* rw  = sm + C_RW;
    float* ab  = sm + C_AB;
    float* red = sm + C_RED;
    int nt = blockIdx.x, b = blockIdx.y, t = threadIdx.x;
    int w = t >> 5, lane = t & 31;
    float* hid = sm + C_HID + w*512;
    int n0 = nt * 8;
    if (t < 192) { ew[t] = expand_w[t]; rw[t] = reduce_w[t]; }
    if (t < 96) ab[t] = (t < 48) ? g_ab1[b*48 + t] : g_ab2[b*48 + (t-48)];
    for (int i = t; i < 10*392; i += 256) {
        int r = i / 392, m = i - r*392;
        int n = n0 - 1 + r;
        at[i] = (n >= 0 && n < 3136) ? g_attn[((size_t)b*3136 + n)*392 + m] : 0.f;
    }
    __syncthreads();
    #pragma unroll
    for (int k = 0; k < 3; k++) {
        int c = w + k*8;
        float A1 = ab[c*2], B1 = ab[c*2+1];
        float A2 = ab[48 + c*2], B2 = ab[49 + c*2];
        const float* wp = ew + c*8;
        for (int i = lane; i < 510; i += 32) {
            int r = i / 51, mm = i - r*51;
            int n = n0 - 1 + r;
            float v = 0.f;
            if (mm >= 1 && mm <= 49 && n >= 0 && n < 3136) {
                const float* sp = at + r*392 + (mm - 1);
                float hsum = 0.f;
                #pragma unroll
                for (int hh = 0; hh < 8; hh++) hsum += sp[hh*49] * wp[hh];
                v = swishf(A1*hsum + B1);
            }
            hid[i] = v;
        }
        __syncwarp();
        float lw[9];
        #pragma unroll
        for (int i = 0; i < 9; i++) lw[i] = dw_w[c*9 + i];
        for (int o = lane; o < 392; o += 32) {
            int ny = o / 49, m = o - ny*49;
            float a = 0.f;
            #pragma unroll
            for (int dy = 0; dy < 3; dy++)
                #pragma unroll
                for (int dx = 0; dx < 3; dx++)
                    a += hid[(ny+dy)*51 + m+dx] * lw[dy*3+dx];
            dws[(ny*24 + c)*49 + m] = swishf(A2*a + B2);
        }
        __syncwarp();
    }
    __syncthreads();
    float lsum = 0.f, lsq = 0.f;
    for (int o = t; o < 392; o += 256) {
        int ny = o / 49, m = o - ny*49;
        int n = n0 + ny;
        float in[24];
        #pragma unroll
        for (int c = 0; c < 24; c++) in[c] = dws[(ny*24 + c)*49 + m];
        size_t ob = ((size_t)b*3136 + n)*392 + m;
        #pragma unroll
        for (int h = 0; h < 8; h++) {
            float r = 0.f;
            #pragma unroll
            for (int c = 0; c < 24; c++) r += in[c] * rw[h*24 + c];
            __nv_bfloat16 hh, ll; bsplit(r, hh, ll);
            g_ath[ob + h*49] = hh;
            g_atl[ob + h*49] = ll;
            lsum += r; lsq += r*r;
        }
    }
    red[t] = lsum; red[256 + t] = lsq;
    __syncthreads();
    for (int st = 128; st; st >>= 1) {
        if (t < st) { red[t] += red[t+st]; red[256+t] += red[256+t+st]; }
        __syncthreads();
    }
    if (!t) {
        g_part3[(b*392 + nt)*2]     = red[0];
        g_part3[(b*392 + nt)*2 + 1] = red[256];
    }
}

// ---------------- 9. GEMM2 (bf16x3 mma.sync) ----------------
#define G2_BUF 15360
#define G2_AH 0
#define G2_AL 5120
#define G2_BH 10240
#define G2_BL 12800
#define G2_SMEM (G2_BUF*2*2)
__device__ __forceinline__ void g2_load(uint32_t sb, int b, int nt0, int ct0,
                                        int kt, int p, int t) {
    int k0 = kt*32;
    uint32_t base = sb + (uint32_t)p*G2_BUF*2;
    #pragma unroll
    for (int rr = 0; rr < 2; rr++) {
        int idx = t + rr*256;
        int row = idx >> 2, q = idx & 3;
        int n = nt0 + row, j0 = k0 + q*8;
        bool v = (n < 3136) && (j0 < 392);
        size_t e = ((size_t)b*3136 + (n < 3136 ? n : 0))*392 + (j0 < 392 ? j0 : 0);
        uint32_t doff = (uint32_t)(row*40 + q*8)*2;
        cpa16(base + G2_AH*2 + doff, g_ath + e, v);
        cpa16(base + G2_AL*2 + doff, g_atl + e, v);
    }
    {
        int idx = t;
        int row = idx >> 2, q = idx & 3;
        int c = ct0 + row, j0 = k0 + q*8;
        bool v = j0 < 392;
        size_t e = ((size_t)b*512 + c)*392 + (v ? j0 : 0);
        uint32_t doff = (uint32_t)(row*40 + q*8)*2;
        cpa16(base + G2_BH*2 + doff, g_wvh + e, v);
        cpa16(base + G2_BL*2 + doff, g_wvl + e, v);
    }
}

__global__ __launch_bounds__(256) void k_gemm2_mma(float* __restrict__ out) {
    extern __shared__ __nv_bfloat16 dsm2[];
    uint32_t sb = smem_u32(dsm2);
    int b = blockIdx.z, nt0 = blockIdx.y*128, ct0 = blockIdx.x*64;
    int t = threadIdx.x, w = t >> 5, lane = t & 31;
    int wn = (w & 3)*32, wc = (w >> 2)*32;
    float acc[2][4][4];
    #pragma unroll
    for (int i = 0; i < 2; i++)
        #pragma unroll
        for (int j = 0; j < 4; j++)
            #pragma unroll
            for (int k = 0; k < 4; k++) acc[i][j][k] = 0.f;

    g2_load(sb, b, nt0, ct0, 0, 0, t);
    cp_commit();
    for (int kt = 0; kt < 13; kt++) {
        if (kt < 12) {
            g2_load(sb, b, nt0, ct0, kt+1, (kt+1) & 1, t);
            cp_commit();
            cp_wait1();
        } else cp_wait0();
        __syncthreads();
        uint32_t base = sb + (uint32_t)(kt & 1)*G2_BUF*2;
        #pragma unroll
        for (int kk = 0; kk < 2; kk++) {
            int kb = kk*16;
            uint32_t ah[2][4], al[2][4];
            #pragma unroll
            for (int mt = 0; mt < 2; mt++) {
                int row = wn + mt*16 + (lane & 15);
                int col = kb + ((lane & 16) ? 8 : 0);
                uint32_t off = (uint32_t)(row*40 + col)*2;
                ldm_x4(ah[mt], base + G2_AH*2 + off);
                ldm_x4(al[mt], base + G2_AL*2 + off);
            }
            uint32_t bh[4][2], bl[4][2];
            #pragma unroll
            for (int p = 0; p < 2; p++) {
                int crow = wc + p*16 + (lane & 7) + ((lane & 16) ? 8 : 0);
                int col = kb + ((lane & 8) ? 8 : 0);
                uint32_t off = (uint32_t)(crow*40 + col)*2;
                uint32_t r4[4];
                ldm_x4(r4, base + G2_BH*2 + off);
                bh[2*p][0]=r4[0]; bh[2*p][1]=r4[1]; bh[2*p+1][0]=r4[2]; bh[2*p+1][1]=r4[3];
                ldm_x4(r4, base + G2_BL*2 + off);
                bl[2*p][0]=r4[0]; bl[2*p][1]=r4[1]; bl[2*p+1][0]=r4[2]; bl[2*p+1][1]=r4[3];
            }
            #pragma unroll
            for (int mt = 0; mt < 2; mt++)
                #pragma unroll
                for (int ct = 0; ct < 4; ct++) {
                    mma_bf16(acc[mt][ct], ah[mt], bh[ct]);
                    mma_bf16(acc[mt][ct], al[mt], bh[ct]);
                    mma_bf16(acc[mt][ct], ah[mt], bl[ct]);
                }
        }
        __syncthreads();
    }
    int nrow = nt0 + wn + (lane >> 2);
    #pragma unroll
    for (int mt = 0; mt < 2; mt++) {
        #pragma unroll
        for (int ct = 0; ct < 4; ct++) {
            int c0 = ct0 + wc + ct*8 + ((lane & 3) << 1);
            float b0 = g_bias2[b*512 + c0];
            float b1 = g_bias2[b*512 + c0 + 1];
            #pragma unroll
            for (int half = 0; half < 2; half++) {
                int n = nrow + mt*16 + half*8;
                if (n < 3136) {
                    size_t o = ((size_t)b*3136 + n)*512 + c0;
                    *(float2*)&out[o] = make_float2(acc[mt][ct][half*2] + b0,
                                                    acc[mt][ct][half*2+1] + b1);
                }
            }
        }
    }
}

// ---------------- launcher ----------------
extern "C" void kernel_launch(void* const* d_in, const int* in_sizes, int n_in,
                              void* d_out, int out_size) {
    const float* x        = (const float*)d_in[0];
    const float* q_w      = (const float*)d_in[1];
    const float* down_w   = (const float*)d_in[2];
    const float* kv_w     = (const float*)d_in[3];
    const float* proj_w   = (const float*)d_in[4];
    const float* proj_b   = (const float*)d_in[5];
    const float* rel_bias = (const float*)d_in[6];
    const float* expand_w = (const float*)d_in[7];
    const float* gn1_s    = (const float*)d_in[8];
    const float* gn1_b    = (const float*)d_in[9];
    const float* dw_w     = (const float*)d_in[10];
    const float* gn2_s    = (const float*)d_in[11];
    const float* gn2_b    = (const float*)d_in[12];
    const float* reduce_w = (const float*)d_in[13];
    const float* gn3_s    = (const float*)d_in[14];
    const float* gn3_b    = (const float*)d_in[15];
    float* out = (float*)d_out;

    float *ab1, *ab2, *ab3, *p1, *p2, *p3;
    cudaGetSymbolAddress((void**)&ab1, g_ab1);
    cudaGetSymbolAddress((void**)&ab2, g_ab2);
    cudaGetSymbolAddress((void**)&ab3, g_ab3);
    cudaGetSymbolAddress((void**)&p1, g_part1);
    cudaGetSymbolAddress((void**)&p2, g_part2);
    cudaGetSymbolAddress((void**)&p3, g_part3);

    cudaFuncSetAttribute(k_gemm1_mma, cudaFuncAttributeMaxDynamicSharedMemorySize, G1_SMEM);
    cudaFuncSetAttribute(k_gemm2_mma, cudaFuncAttributeMaxDynamicSharedMemorySize, G2_SMEM);
    cudaFuncSetAttribute(k_dw_gn2,    cudaFuncAttributeMaxDynamicSharedMemorySize, B_SMEM);
    cudaFuncSetAttribute(k_dla_out,   cudaFuncAttributeMaxDynamicSharedMemorySize, C_SMEM);

    k_xsplit<<<dim3(98, 16, BB), 256>>>(x);
    k_down<<<BB*CCH, 256>>>(x, down_w);
    k_kv  <<<dim3(4, 7, BB), 256>>>(kv_w);
    k_wqk_split<<<dim3(2, 8, BB), 256>>>(q_w);
    k_wvp <<<dim3(7, 8, BB), 256>>>(proj_w);
    k_gemm1_mma<<<dim3(4, 25, BB), 256, G1_SMEM>>>(rel_bias);
    k_softmax_gn1<<<dim3(392, BB), 256>>>(expand_w);
    k_stats_final<<<BB*3, 256>>>(gn1_s, gn1_b, ab1, p1, 3, 392);
    k_dw_gn2<<<dim3(196, BB), 256, B_SMEM>>>(dw_w, expand_w);
    k_stats_final<<<BB*3, 256>>>(gn2_s, gn2_b, ab2, p2, 3, 196);
    k_dla_out<<<dim3(392, BB), 256, C_SMEM>>>(dw_w, expand_w, reduce_w);
    k_stats_final<<<BB, 256>>>(gn3_s, gn3_b, ab3, p3, 1, 392);
    k_wvpsplit<<<dim3(13, 16, BB), 256>>>();
    k_wvpbias<<<BB, 512>>>(proj_b);
    k_gemm2_mma<<<dim3(8, 25, BB), 256, G2_SMEM>>>(out);
}

// round 7
// speedup vs baseline: 1.9811x; 1.0557x over previous
#include <cuda_runtime.h>
#include <cuda_bf16.h>
#include <math.h>
#include <stdint.h>

#define BB    16
#define CCH   512
#define NN    3136
#define NKK   49
#define HEADS 8
#define JJ    392
#define HIDC  24
#define SCALE 0.125f

// ---------------- device scratch ----------------
__device__ float g_kvx[BB*NKK*CCH];
__device__ float g_kv [BB*NKK*1024];
__device__ float g_Wvp[BB*JJ*CCH];
__device__ __nv_bfloat16 g_xTh[(size_t)BB*NN*CCH];
__device__ __nv_bfloat16 g_xTl[(size_t)BB*NN*CCH];
__device__ __nv_bfloat16 g_wqh[BB*JJ*CCH];
__device__ __nv_bfloat16 g_wql[BB*JJ*CCH];
__device__ __nv_bfloat16 g_wvh[BB*CCH*JJ];
__device__ __nv_bfloat16 g_wvl[BB*CCH*JJ];
__device__ float g_attn[(size_t)BB*NN*JJ];
__device__ __nv_bfloat16 g_ath[(size_t)BB*NN*JJ];
__device__ __nv_bfloat16 g_atl[(size_t)BB*NN*JJ];
__device__ float g_part1[BB*49*36];
__device__ float g_part2[BB*3*196*2];
__device__ float g_part3[BB*392*2];
__device__ float g_ab1[BB*HIDC*2];
__device__ float g_ab2[BB*HIDC*2];
__device__ float g_ab3[BB*HEADS*2];
__device__ float g_bias2[BB*CCH];

__device__ __forceinline__ float swishf(float x) { return x / (1.f + __expf(-x)); }

__device__ __forceinline__ void bsplit(float v, __nv_bfloat16& h, __nv_bfloat16& l) {
    h = __float2bfloat16(v);
    l = __float2bfloat16(v - __bfloat162float(h));
}

__device__ __forceinline__ uint32_t smem_u32(const void* p) {
    uint32_t a;
    asm("{ .reg .u64 t; cvta.to.shared.u64 t, %1; cvt.u32.u64 %0, t; }" : "=r"(a) : "l"(p));
    return a;
}
__device__ __forceinline__ void ldm_x4(uint32_t* r, uint32_t addr) {
    asm volatile("ldmatrix.sync.aligned.m8n8.x4.shared.b16 {%0,%1,%2,%3}, [%4];"
        : "=r"(r[0]), "=r"(r[1]), "=r"(r[2]), "=r"(r[3]) : "r"(addr));
}
__device__ __forceinline__ void ldm_x2(uint32_t* r, uint32_t addr) {
    asm volatile("ldmatrix.sync.aligned.m8n8.x2.shared.b16 {%0,%1}, [%2];"
        : "=r"(r[0]), "=r"(r[1]) : "r"(addr));
}
__device__ __forceinline__ void mma_bf16(float* c, const uint32_t* a, const uint32_t* b) {
    asm volatile(
        "mma.sync.aligned.m16n8k16.row.col.f32.bf16.bf16.f32 "
        "{%0,%1,%2,%3}, {%4,%5,%6,%7}, {%8,%9}, {%0,%1,%2,%3};"
        : "+f"(c[0]), "+f"(c[1]), "+f"(c[2]), "+f"(c[3])
        : "r"(a[0]), "r"(a[1]), "r"(a[2]), "r"(a[3]), "r"(b[0]), "r"(b[1]));
}
__device__ __forceinline__ void cpa16(uint32_t dst, const void* src, bool v) {
    int sz = v ? 16 : 0;
    asm volatile("cp.async.cg.shared.global [%0], [%1], 16, %2;"
        :: "r"(dst), "l"(src), "r"(sz) : "memory");
}
__device__ __forceinline__ void cp_commit() {
    asm volatile("cp.async.commit_group;" ::: "memory");
}
__device__ __forceinline__ void cp_wait1() {
    asm volatile("cp.async.wait_group 1;" ::: "memory");
}
__device__ __forceinline__ void cp_wait0() {
    asm volatile("cp.async.wait_group 0;" ::: "memory");
}

// ---------------- 1. depthwise 8x8/8 downsample ----------------
__global__ void k_down(const float* __restrict__ x, const float* __restrict__ down_w) {
    int bc = blockIdx.x, c = bc & 511, b = bc >> 9;
    __shared__ float plane[3136];
    __shared__ float w[64];
    const float* xp = x + (size_t)bc * 3136;
    for (int i = threadIdx.x; i < 3136; i += 256) plane[i] = xp[i];
    if (threadIdx.x < 64) w[threadIdx.x] = down_w[c*64 + threadIdx.x];
    __syncthreads();
    if (threadIdx.x < 49) {
        int my = threadIdx.x / 7, mx = threadIdx.x % 7;
        float s = 0.f;
        #pragma unroll
        for (int i = 0; i < 8; i++)
            #pragma unroll
            for (int j = 0; j < 8; j++)
                s += plane[(my*8+i)*56 + mx*8 + j] * w[i*8+j];
        g_kvx[(b*49 + threadIdx.x)*512 + c] = s;
    }
}

// ---------------- 2. kv = kvx @ kv_w ----------------
__global__ void k_kv(const float* __restrict__ kv_w) {
    int b = blockIdx.z, m0 = blockIdx.y * 7, oc = blockIdx.x;
    __shared__ float a[7][512];
    for (int i = threadIdx.x; i < 7*512; i += 256)
        a[i >> 9][i & 511] = g_kvx[(b*49 + m0 + (i >> 9))*512 + (i & 511)];
    __syncthreads();
    int o = oc*256 + threadIdx.x;
    float acc[7] = {0,0,0,0,0,0,0};
    for (int c = 0; c < 512; c++) {
        float w = kv_w[c*1024 + o];
        #pragma unroll
        for (int mm = 0; mm < 7; mm++) acc[mm] += a[mm][c] * w;
    }
    #pragma unroll
    for (int mm = 0; mm < 7; mm++)
        g_kv[(b*49 + m0 + mm)*1024 + o] = acc[mm];
}

// ---------------- 3. Wqk fused compute + bf16 split ----------------
__global__ __launch_bounds__(256) void k_wqk_split(const float* __restrict__ q_w) {
    int half = blockIdx.x, h = blockIdx.y, b = blockIdx.z;
    __shared__ float ks[49][64];
    for (int i = threadIdx.x; i < 49*64; i += 256)
        ks[i >> 6][i & 63] = g_kv[(b*49 + (i >> 6))*1024 + h*64 + (i & 63)];
    __syncthreads();
    int cin = half*256 + threadIdx.x;
    float acc[49];
    #pragma unroll
    for (int m = 0; m < 49; m++) acc[m] = 0.f;
    const float4* q4 = (const float4*)(q_w + (size_t)cin*512 + h*64);
    const float4* ks4 = (const float4*)&ks[0][0];
    for (int d4 = 0; d4 < 16; d4++) {
        float4 q = __ldg(q4 + d4);
        #pragma unroll
        for (int m = 0; m < 49; m++) {
            float4 k = ks4[m*16 + d4];
            acc[m] += q.x*k.x + q.y*k.y + q.z*k.z + q.w*k.w;
        }
    }
    size_t obase = ((size_t)b*392 + h*49)*512 + cin;
    #pragma unroll
    for (int m = 0; m < 49; m++) {
        float v = acc[m] * SCALE;
        __nv_bfloat16 hh, ll; bsplit(v, hh, ll);
        g_wqh[obase + (size_t)m*512] = hh;
        g_wql[obase + (size_t)m*512] = ll;
    }
}

// ---------------- 4. Wvp ----------------
__global__ void k_wvp(const float* __restrict__ proj_w) {
    int b = blockIdx.z, h = blockIdx.y, mc = blockIdx.x * 7;
    __shared__ float vs[7][64];
    for (int i = threadIdx.x; i < 7*64; i += 256)
        vs[i >> 6][i & 63] = g_kv[(b*49 + mc + (i >> 6))*1024 + 512 + h*64 + (i & 63)];
    __syncthreads();
    int t = threadIdx.x;
    float acc[7][2] = {{0}};
    for (int d = 0; d < 64; d++) {
        float w0 = proj_w[(h*64+d)*512 + t];
        float w1 = proj_w[(h*64+d)*512 + 256 + t];
        #pragma unroll
        for (int mm = 0; mm < 7; mm++) {
            float vv = vs[mm][d];
            acc[mm][0] += vv * w0;
            acc[mm][1] += vv * w1;
        }
    }
    #pragma unroll
    for (int mm = 0; mm < 7; mm++) {
        int j = h*49 + mc + mm;
        g_Wvp[(b*392 + j)*512 + t]       = acc[mm][0];
        g_Wvp[(b*392 + j)*512 + 256 + t] = acc[mm][1];
    }
}

// ---------------- 4b. transpose+split x ----------------
__global__ void k_xsplit(const float* __restrict__ x) {
    int tn = blockIdx.x, tc = blockIdx.y, b = blockIdx.z;
    __shared__ float tile[32][33];
    int a = threadIdx.x >> 5, q = threadIdx.x & 31;
    #pragma unroll
    for (int r = 0; r < 4; r++) {
        int cc = tc*32 + a + r*8, nn = tn*32 + q;
        tile[a + r*8][q] = x[((size_t)b*512 + cc)*3136 + nn];
    }
    __syncthreads();
    #pragma unroll
    for (int r = 0; r < 4; r++) {
        int nn = tn*32 + a + r*8, cc = tc*32 + q;
        float v = tile[q][a + r*8];
        __nv_bfloat16 h, l; bsplit(v, h, l);
        size_t o = ((size_t)b*3136 + nn)*512 + cc;
        g_xTh[o] = h; g_xTl[o] = l;
    }
}

// ---------------- 4d. transpose+scale+split Wvp ----------------
__global__ void k_wvpsplit(void) {
    int tj = blockIdx.x, tc = blockIdx.y, b = blockIdx.z;
    __shared__ float tile[32][33];
    int a = threadIdx.x >> 5, q = threadIdx.x & 31;
    #pragma unroll
    for (int r = 0; r < 4; r++) {
        int jj = tj*32 + a + r*8, cc = tc*32 + q;
        float v = 0.f;
        if (jj < 392) v = g_Wvp[((size_t)b*392 + jj)*512 + cc] * g_ab3[(b*8 + jj/49)*2];
        tile[a + r*8][q] = v;
    }
    __syncthreads();
    #pragma unroll
    for (int r = 0; r < 4; r++) {
        int cc = tc*32 + a + r*8, jj = tj*32 + q;
        if (jj < 392) {
            float v = tile[q][a + r*8];
            __nv_bfloat16 h, l; bsplit(v, h, l);
            size_t o = ((size_t)b*512 + cc)*392 + jj;
            g_wvh[o] = h; g_wvl[o] = l;
        }
    }
}

// ---------------- 4e. bias2 ----------------
__global__ void k_wvpbias(const float* __restrict__ proj_b) {
    int b = blockIdx.x, c = threadIdx.x;
    float acc = 0.f;
    for (int j = 0; j < 392; j++)
        acc += g_ab3[(b*8 + j/49)*2 + 1] * g_Wvp[((size_t)b*392 + j)*512 + c];
    g_bias2[b*512 + c] = acc + proj_b[c];
}

// ---------------- 5. GEMM1 fused (bf16x3 mma.sync, 64n x 416j tiles,
//                    epilogue: rel_bias + softmax + Gram partials + attn write) ----------------
#define G1_ABUF  5120u    // bytes per A matrix (64 rows x 40 bf16)
#define G1_BBASE 20480u
#define G1_BBUF  33280u   // bytes per B matrix (416 rows x 40 bf16)
#define G1_SMEM  153600
__device__ __forceinline__ void g1f_load(uint32_t sb, int b, int nt0, int kt, int p, int t) {
    int k0 = kt*32;
    {
        int row = t >> 2, q = t & 3;
        size_t e = ((size_t)b*3136 + nt0 + row)*512 + k0 + q*8;
        uint32_t doff = (uint32_t)(row*40 + q*8)*2;
        cpa16(sb + (p*2+0)*G1_ABUF + doff, g_xTh + e, true);
        cpa16(sb + (p*2+1)*G1_ABUF + doff, g_xTl + e, true);
    }
    #pragma unroll
    for (int rr = 0; rr < 13; rr++) {
        int idx = rr*256 + t;
        int hl = idx >= 1664;
        int ii = idx - hl*1664;
        int row = ii >> 2, q = ii & 3;
        bool v = row < 392;
        size_t e = ((size_t)b*392 + (v ? row : 0))*512 + k0 + q*8;
        uint32_t doff = (uint32_t)(row*40 + q*8)*2;
        const __nv_bfloat16* src = hl ? g_wql : g_wqh;
        cpa16(sb + G1_BBASE + (p*2+hl)*G1_BBUF + doff, src + e, v);
    }
}

__global__ __launch_bounds__(256) void k_gemm1_fused(const float* __restrict__ rel_bias) {
    extern __shared__ char smraw[];
    uint32_t sb = smem_u32(smraw);
    int b = blockIdx.y, nt0 = blockIdx.x * 64;
    int t = threadIdx.x, w = t >> 5, lane = t & 31;
    int wn = (w & 1)*32, wj = (w >> 1)*104;
    float acc[2][13][4];
    #pragma unroll
    for (int i = 0; i < 2; i++)
        #pragma unroll
        for (int j = 0; j < 13; j++)
            #pragma unroll
            for (int k = 0; k < 4; k++) acc[i][j][k] = 0.f;

    g1f_load(sb, b, nt0, 0, 0, t);
    cp_commit();
    for (int kt = 0; kt < 16; kt++) {
        if (kt < 15) {
            g1f_load(sb, b, nt0, kt+1, (kt+1) & 1, t);
            cp_commit();
            cp_wait1();
        } else cp_wait0();
        __syncthreads();
        int p = kt & 1;
        uint32_t pAh = sb + (p*2+0)*G1_ABUF;
        uint32_t pAl = sb + (p*2+1)*G1_ABUF;
        uint32_t pBh = sb + G1_BBASE + (p*2+0)*G1_BBUF;
        uint32_t pBl = sb + G1_BBASE + (p*2+1)*G1_BBUF;
        #pragma unroll
        for (int kk = 0; kk < 2; kk++) {
            int kb = kk*16;
            uint32_t ah[2][4], al[2][4];
            int arow = wn + (lane & 15);
            int acol = kb + ((lane & 16) ? 8 : 0);
            ldm_x4(ah[0], pAh + (uint32_t)(arow*40 + acol)*2);
            ldm_x4(ah[1], pAh + (uint32_t)((arow+16)*40 + acol)*2);
            ldm_x4(al[0], pAl + (uint32_t)(arow*40 + acol)*2);
            ldm_x4(al[1], pAl + (uint32_t)((arow+16)*40 + acol)*2);
            #pragma unroll
            for (int p2 = 0; p2 < 6; p2++) {
                int jrow = wj + p2*16 + (lane & 7) + ((lane & 16) ? 8 : 0);
                int col = kb + ((lane & 8) ? 8 : 0);
                uint32_t off = (uint32_t)(jrow*40 + col)*2;
                uint32_t rh[4], rl[4];
                ldm_x4(rh, pBh + off);
                ldm_x4(rl, pBl + off);
                #pragma unroll
                for (int mt = 0; mt < 2; mt++)
                    #pragma unroll
                    for (int e = 0; e < 2; e++) {
                        mma_bf16(acc[mt][2*p2+e], ah[mt], &rh[2*e]);
                        mma_bf16(acc[mt][2*p2+e], al[mt], &rh[2*e]);
                        mma_bf16(acc[mt][2*p2+e], ah[mt], &rl[2*e]);
                    }
            }
            {
                int jrow = wj + 96 + (lane & 7);
                int col = kb + ((lane & 8) ? 8 : 0);
                uint32_t off = (uint32_t)(jrow*40 + col)*2;
                uint32_t bh2[2], bl2[2];
                ldm_x2(bh2, pBh + off);
                ldm_x2(bl2, pBl + off);
                #pragma unroll
                for (int mt = 0; mt < 2; mt++) {
                    mma_bf16(acc[mt][12], ah[mt], bh2);
                    mma_bf16(acc[mt][12], al[mt], bh2);
                    mma_bf16(acc[mt][12], ah[mt], bl2);
                }
            }
        }
        __syncthreads();
    }
    // ---- epilogue: stage logits in SMEM (reuse operand buffers) ----
    float* S = (float*)smraw;            // [64][400]
    float* Gred = S + 64*400;            // [8][36]
    #pragma unroll
    for (int mt = 0; mt < 2; mt++) {
        int nl = wn + mt*16 + (lane >> 2);
        #pragma unroll
        for (int jt = 0; jt < 13; jt++) {
            int j0 = wj + jt*8 + ((lane & 3) << 1);
            if (j0 < 392) {
                S[nl*400 + j0]       = acc[mt][jt][0];
                S[nl*400 + j0 + 1]   = acc[mt][jt][1];
                S[(nl+8)*400 + j0]   = acc[mt][jt][2];
                S[(nl+8)*400 + j0+1] = acc[mt][jt][3];
            }
        }
    }
    __syncthreads();
    // ---- softmax per (n,h) row, adding rel_bias ----
    #pragma unroll
    for (int rr = 0; rr < 2; rr++) {
        int row = t + rr*256;
        int n = row >> 3, h = row & 7;
        float* p = S + n*400 + h*49;
        const float* rb = rel_bias + (size_t)(nt0 + n)*49;
        float mx = -1e30f;
        for (int i = 0; i < 49; i++) {
            float lv = p[i] + __ldg(rb + i);
            p[i] = lv;
            mx = fmaxf(mx, lv);
        }
        float sum = 0.f;
        for (int i = 0; i < 49; i++) { float e = __expf(p[i] - mx); p[i] = e; sum += e; }
        float inv = 1.f / sum;
        for (int i = 0; i < 49; i++) p[i] *= inv;
    }
    __syncthreads();
    // ---- Gram partials (36 upper-tri entries of 8x8) ----
    float g[36];
    #pragma unroll
    for (int k = 0; k < 36; k++) g[k] = 0.f;
    for (int pos = t; pos < 64*49; pos += 256) {
        int n = pos / 49, m = pos - n*49;
        float a[8];
        #pragma unroll
        for (int h = 0; h < 8; h++) a[h] = S[n*400 + h*49 + m];
        int k = 0;
        #pragma unroll
        for (int h = 0; h < 8; h++)
            #pragma unroll
            for (int h2 = h; h2 < 8; h2++) { g[k] += a[h]*a[h2]; k++; }
    }
    // ---- write softmaxed attn ----
    size_t ob = ((size_t)b*3136 + nt0)*392;
    for (int i = t; i < 64*392; i += 256) {
        int n = i / 392, c = i - n*392;
        g_attn[ob + i] = S[n*400 + c];
    }
    // ---- reduce Gram across block ----
    #pragma unroll
    for (int s = 16; s; s >>= 1)
        #pragma unroll
        for (int k = 0; k < 36; k++) g[k] += __shfl_xor_sync(0xffffffffu, g[k], s);
    if (lane == 0)
        #pragma unroll
        for (int k = 0; k < 36; k++) Gred[w*36 + k] = g[k];
    __syncthreads();
    if (t < 36) {
        float s = 0.f;
        #pragma unroll
        for (int ww = 0; ww < 8; ww++) s += Gred[ww*36 + t];
        g_part1[((size_t)b*49 + blockIdx.x)*36 + t] = s;
    }
}

// ---------------- 6. gn1 finalize from Gram ----------------
__global__ void k_gn1_final(const float* __restrict__ gs, const float* __restrict__ gb,
                            const float* __restrict__ ew) {
    int b = blockIdx.x, t = threadIdx.x;   // 64 threads
    __shared__ float M36[36];
    __shared__ float Mf[64];
    __shared__ float s1s[24], sqs[24];
    __shared__ float mg[3], rg[3];
    if (t < 36) {
        float s = 0.f;
        for (int nt = 0; nt < 49; nt++) s += g_part1[((size_t)b*49 + nt)*36 + t];
        M36[t] = s;
    }
    __syncthreads();
    if (t == 0) {
        int k = 0;
        for (int h = 0; h < 8; h++)
            for (int h2 = h; h2 < 8; h2++) { Mf[h*8+h2] = M36[k]; Mf[h2*8+h] = M36[k]; k++; }
    }
    __syncthreads();
    if (t < 24) {
        float wv[8], sw = 0.f;
        #pragma unroll
        for (int h = 0; h < 8; h++) { wv[h] = ew[t*8+h]; sw += wv[h]; }
        float sq = 0.f;
        #pragma unroll
        for (int h = 0; h < 8; h++)
            #pragma unroll
            for (int h2 = 0; h2 < 8; h2++) sq += wv[h]*wv[h2]*Mf[h*8+h2];
        s1s[t] = 3136.f * sw;
        sqs[t] = sq;
    }
    __syncthreads();
    if (t < 3) {
        float s1 = 0.f, sq = 0.f;
        for (int c = 0; c < 8; c++) { s1 += s1s[t*8+c]; sq += sqs[t*8+c]; }
        float cnt = 8.f*3136.f*49.f;
        float mean = s1/cnt;
        float var  = sq/cnt - mean*mean;
        mg[t] = mean;
        rg[t] = rsqrtf(var + 1e-5f);
    }
    __syncthreads();
    if (t < 24) {
        float A = rg[t>>3]*gs[t];
        g_ab1[(b*24 + t)*2]     = A;
        g_ab1[(b*24 + t)*2 + 1] = gb[t] - mg[t>>3]*A;
    }
}

// ---------------- stats finalize (gn2/gn3) ----------------
__global__ void k_stats_final(const float* __restrict__ gs, const float* __restrict__ gb,
                              float* __restrict__ ab, const float* __restrict__ part,
                              int G, int npart) {
    int b = blockIdx.x / G, g = blockIdx.x % G;
    const float* p = part + (size_t)(b*G + g)*npart*2;
    float sm = 0.f, sq = 0.f;
    for (int i = threadIdx.x; i < npart; i += 256) { sm += p[2*i]; sq += p[2*i+1]; }
    __shared__ float rs[256], rq[256];
    __shared__ float mean_s, rstd_s;
    int t = threadIdx.x;
    rs[t] = sm; rq[t] = sq;
    __syncthreads();
    for (int st = 128; st; st >>= 1) {
        if (t < st) { rs[t] += rs[t+st]; rq[t] += rq[t+st]; }
        __syncthreads();
    }
    if (!t) {
        float cnt  = 8.f * 3136.f * 49.f;
        float mean = rs[0] / cnt;
        float var  = rq[0] / cnt - mean*mean;
        mean_s = mean;
        rstd_s = rsqrtf(var + 1e-5f);
    }
    __syncthreads();
    if (t < 8) {
        int c = g*8 + t;
        float A = rstd_s * gs[c];
        int CH = G*8;
        ab[(b*CH + c)*2]     = A;
        ab[(b*CH + c)*2 + 1] = gb[c] - mean_s*A;
    }
}

// ---------------- 7. pass B: warp-parallel expand+dw -> gn2 partials ----------------
#define B_AT  0
#define B_HID 7056
#define B_EW  14416
#define B_AB  14608
#define B_RED 14656
#define B_TOT (14656 + 1536)
#define B_SMEM (B_TOT*4)
__global__ __launch_bounds__(256) void k_dw_gn2(const float* __restrict__ dw_w,
                                                const float* __restrict__ expand_w) {
    extern __shared__ float sm[];
    float* at  = sm + B_AT;
    float* ew  = sm + B_EW;
    float* ab  = sm + B_AB;
    float* red = sm + B_RED;
    int nt = blockIdx.x, b = blockIdx.y, t = threadIdx.x;
    int w = t >> 5, lane = t & 31;
    float* hid = sm + B_HID + w*920;
    int n0 = nt * 16;
    if (t < 192) ew[t] = expand_w[t];
    if (t >= 192 && t < 240) ab[t-192] = g_ab1[b*48 + (t-192)];
    for (int i = t; i < 18*392; i += 256) {
        int r = i / 392, m = i - r*392;
        int n = n0 - 1 + r;
        at[i] = (n >= 0 && n < 3136) ? g_attn[((size_t)b*3136 + n)*392 + m] : 0.f;
    }
    __syncthreads();
    float sk[3] = {0,0,0}, qk[3] = {0,0,0};
    #pragma unroll
    for (int k = 0; k < 3; k++) {
        int c = w + k*8;
        float A1 = ab[c*2], B1 = ab[c*2+1];
        const float* wp = ew + c*8;
        for (int i = lane; i < 918; i += 32) {
            int r = i / 51, mm = i - r*51;
            int n = n0 - 1 + r;
            float v = 0.f;
            if (mm >= 1 && mm <= 49 && n >= 0 && n < 3136) {
                const float* sp = at + r*392 + (mm - 1);
                float hsum = 0.f;
                #pragma unroll
                for (int hh = 0; hh < 8; hh++) hsum += sp[hh*49] * wp[hh];
                v = swishf(A1*hsum + B1);
            }
            hid[i] = v;
        }
        __syncwarp();
        float lw[9];
        #pragma unroll
        for (int i = 0; i < 9; i++) lw[i] = dw_w[c*9 + i];
        for (int o = lane; o < 784; o += 32) {
            int ny = o / 49, m = o - ny*49;
            float a = 0.f;
            #pragma unroll
            for (int dy = 0; dy < 3; dy++)
                #pragma unroll
                for (int dx = 0; dx < 3; dx++)
                    a += hid[(ny+dy)*51 + m+dx] * lw[dy*3+dx];
            sk[k] += a; qk[k] += a*a;
        }
        __syncwarp();
    }
    #pragma unroll
    for (int g = 0; g < 3; g++) { red[g*256 + t] = sk[g]; red[(3+g)*256 + t] = qk[g]; }
    __syncthreads();
    for (int st = 128; st; st >>= 1) {
        if (t < st)
            #pragma unroll
            for (int g = 0; g < 6; g++) red[g*256 + t] += red[g*256 + t + st];
        __syncthreads();
    }
    if (t < 3) {
        g_part2[((b*3 + t)*196 + nt)*2]     = red[t*256];
        g_part2[((b*3 + t)*196 + nt)*2 + 1] = red[(t+3)*256];
    }
}

// ---------------- 8. pass C: expand+dw+norm2+swish, reduce -> attnF + gn3 ----------------
#define C_AT  0
#define C_HID 3920
#define C_DWS 8016
#define C_EW  17424
#define C_RW  17616
#define C_AB  17808
#define C_RED 17904
#define C_TOT (17904 + 512)
#define C_SMEM (C_TOT*4)
__global__ __launch_bounds__(256) void k_dla_out(const float* __restrict__ dw_w,
                                                 const float* __restrict__ expand_w,
                                                 const float* __restrict__ reduce_w) {
    extern __shared__ float sm[];
    float* at  = sm + C_AT;
    float* dws = sm + C_DWS;
    float* ew  = sm + C_EW;
    float* rw  = sm + C_RW;
    float* ab  = sm + C_AB;
    float* red = sm + C_RED;
    int nt = blockIdx.x, b = blockIdx.y, t = threadIdx.x;
    int w = t >> 5, lane = t & 31;
    float* hid = sm + C_HID + w*512;
    int n0 = nt * 8;
    if (t < 192) { ew[t] = expand_w[t]; rw[t] = reduce_w[t]; }
    if (t < 96) ab[t] = (t < 48) ? g_ab1[b*48 + t] : g_ab2[b*48 + (t-48)];
    for (int i = t; i < 10*392; i += 256) {
        int r = i / 392, m = i - r*392;
        int n = n0 - 1 + r;
        at[i] = (n >= 0 && n < 3136) ? g_attn[((size_t)b*3136 + n)*392 + m] : 0.f;
    }
    __syncthreads();
    #pragma unroll
    for (int k = 0; k < 3; k++) {
        int c = w + k*8;
        float A1 = ab[c*2], B1 = ab[c*2+1];
        float A2 = ab[48 + c*2], B2 = ab[49 + c*2];
        const float* wp = ew + c*8;
        for (int i = lane; i < 510; i += 32) {
            int r = i / 51, mm = i - r*51;
            int n = n0 - 1 + r;
            float v = 0.f;
            if (mm >= 1 && mm <= 49 && n >= 0 && n < 3136) {
                const float* sp = at + r*392 + (mm - 1);
                float hsum = 0.f;
                #pragma unroll
                for (int hh = 0; hh < 8; hh++) hsum += sp[hh*49] * wp[hh];
                v = swishf(A1*hsum + B1);
            }
            hid[i] = v;
        }
        __syncwarp();
        float lw[9];
        #pragma unroll
        for (int i = 0; i < 9; i++) lw[i] = dw_w[c*9 + i];
        for (int o = lane; o < 392; o += 32) {
            int ny = o / 49, m = o - ny*49;
            float a = 0.f;
            #pragma unroll
            for (int dy = 0; dy < 3; dy++)
                #pragma unroll
                for (int dx = 0; dx < 3; dx++)
                    a += hid[(ny+dy)*51 + m+dx] * lw[dy*3+dx];
            dws[(ny*24 + c)*49 + m] = swishf(A2*a + B2);
        }
        __syncwarp();
    }
    __syncthreads();
    float lsum = 0.f, lsq = 0.f;
    for (int o = t; o < 392; o += 256) {
        int ny = o / 49, m = o - ny*49;
        int n = n0 + ny;
        float in[24];
        #pragma unroll
        for (int c = 0; c < 24; c++) in[c] = dws[(ny*24 + c)*49 + m];
        size_t ob = ((size_t)b*3136 + n)*392 + m;
        #pragma unroll
        for (int h = 0; h < 8; h++) {
            float r = 0.f;
            #pragma unroll
            for (int c = 0; c < 24; c++) r += in[c] * rw[h*24 + c];
            __nv_bfloat16 hh, ll; bsplit(r, hh, ll);
            g_ath[ob + h*49] = hh;
            g_atl[ob + h*49] = ll;
            lsum += r; lsq += r*r;
        }
    }
    red[t] = lsum; red[256 + t] = lsq;
    __syncthreads();
    for (int st = 128; st; st >>= 1) {
        if (t < st) { red[t] += red[t+st]; red[256+t] += red[256+t+st]; }
        __syncthreads();
    }
    if (!t) {
        g_part3[(b*392 + nt)*2]     = red[0];
        g_part3[(b*392 + nt)*2 + 1] = red[256];
    }
}

// ---------------- 9. GEMM2 (bf16x3 mma.sync) ----------------
#define G2_BUF 15360
#define G2_AH 0
#define G2_AL 5120
#define G2_BH 10240
#define G2_BL 12800
#define G2_SMEM (G2_BUF*2*2)
__device__ __forceinline__ void g2_load(uint32_t sb, int b, int nt0, int ct0,
                                        int kt, int p, int t) {
    int k0 = kt*32;
    uint32_t base = sb + (uint32_t)p*G2_BUF*2;
    #pragma unroll
    for (int rr = 0; rr < 2; rr++) {
        int idx = t + rr*256;
        int row = idx >> 2, q = idx & 3;
        int n = nt0 + row, j0 = k0 + q*8;
        bool v = (n < 3136) && (j0 < 392);
        size_t e = ((size_t)b*3136 + (n < 3136 ? n : 0))*392 + (j0 < 392 ? j0 : 0);
        uint32_t doff = (uint32_t)(row*40 + q*8)*2;
        cpa16(base + G2_AH*2 + doff, g_ath + e, v);
        cpa16(base + G2_AL*2 + doff, g_atl + e, v);
    }
    {
        int idx = t;
        int row = idx >> 2, q = idx & 3;
        int c = ct0 + row, j0 = k0 + q*8;
        bool v = j0 < 392;
        size_t e = ((size_t)b*512 + c)*392 + (v ? j0 : 0);
        uint32_t doff = (uint32_t)(row*40 + q*8)*2;
        cpa16(base + G2_BH*2 + doff, g_wvh + e, v);
        cpa16(base + G2_BL*2 + doff, g_wvl + e, v);
    }
}

__global__ __launch_bounds__(256) void k_gemm2_mma(float* __restrict__ out) {
    extern __shared__ __nv_bfloat16 dsm2[];
    uint32_t sb = smem_u32(dsm2);
    int b = blockIdx.z, nt0 = blockIdx.y*128, ct0 = blockIdx.x*64;
    int t = threadIdx.x, w = t >> 5, lane = t & 31;
    int wn = (w & 3)*32, wc = (w >> 2)*32;
    float acc[2][4][4];
    #pragma unroll
    for (int i = 0; i < 2; i++)
        #pragma unroll
        for (int j = 0; j < 4; j++)
            #pragma unroll
            for (int k = 0; k < 4; k++) acc[i][j][k] = 0.f;

    g2_load(sb, b, nt0, ct0, 0, 0, t);
    cp_commit();
    for (int kt = 0; kt < 13; kt++) {
        if (kt < 12) {
            g2_load(sb, b, nt0, ct0, kt+1, (kt+1) & 1, t);
            cp_commit();
            cp_wait1();
        } else cp_wait0();
        __syncthreads();
        uint32_t base = sb + (uint32_t)(kt & 1)*G2_BUF*2;
        #pragma unroll
        for (int kk = 0; kk < 2; kk++) {
            int kb = kk*16;
            uint32_t ah[2][4], al[2][4];
            #pragma unroll
            for (int mt = 0; mt < 2; mt++) {
                int row = wn + mt*16 + (lane & 15);
                int col = kb + ((lane & 16) ? 8 : 0);
                uint32_t off = (uint32_t)(row*40 + col)*2;
                ldm_x4(ah[mt], base + G2_AH*2 + off);
                ldm_x4(al[mt], base + G2_AL*2 + off);
            }
            uint32_t bh[4][2], bl[4][2];
            #pragma unroll
            for (int p = 0; p < 2; p++) {
                int crow = wc + p*16 + (lane & 7) + ((lane & 16) ? 8 : 0);
                int col = kb + ((lane & 8) ? 8 : 0);
                uint32_t off = (uint32_t)(crow*40 + col)*2;
                uint32_t r4[4];
                ldm_x4(r4, base + G2_BH*2 + off);
                bh[2*p][0]=r4[0]; bh[2*p][1]=r4[1]; bh[2*p+1][0]=r4[2]; bh[2*p+1][1]=r4[3];
                ldm_x4(r4, base + G2_BL*2 + off);
                bl[2*p][0]=r4[0]; bl[2*p][1]=r4[1]; bl[2*p+1][0]=r4[2]; bl[2*p+1][1]=r4[3];
            }
            #pragma unroll
            for (int mt = 0; mt < 2; mt++)
                #pragma unroll
                for (int ct = 0; ct < 4; ct++) {
                    mma_bf16(acc[mt][ct], ah[mt], bh[ct]);
                    mma_bf16(acc[mt][ct], al[mt], bh[ct]);
                    mma_bf16(acc[mt][ct], ah[mt], bl[ct]);
                }
        }
        __syncthreads();
    }
    int nrow = nt0 + wn + (lane >> 2);
    #pragma unroll
    for (int mt = 0; mt < 2; mt++) {
        #pragma unroll
        for (int ct = 0; ct < 4; ct++) {
            int c0 = ct0 + wc + ct*8 + ((lane & 3) << 1);
            float b0 = g_bias2[b*512 + c0];
            float b1 = g_bias2[b*512 + c0 + 1];
            #pragma unroll
            for (int half = 0; half < 2; half++) {
                int n = nrow + mt*16 + half*8;
                if (n < 3136) {
                    size_t o = ((size_t)b*3136 + n)*512 + c0;
                    *(float2*)&out[o] = make_float2(acc[mt][ct][half*2] + b0,
                                                    acc[mt][ct][half*2+1] + b1);
                }
            }
        }
    }
}

// ---------------- launcher ----------------
extern "C" void kernel_launch(void* const* d_in, const int* in_sizes, int n_in,
                              void* d_out, int out_size) {
    const float* x        = (const float*)d_in[0];
    const float* q_w      = (const float*)d_in[1];
    const float* down_w   = (const float*)d_in[2];
    const float* kv_w     = (const float*)d_in[3];
    const float* proj_w   = (const float*)d_in[4];
    const float* proj_b   = (const float*)d_in[5];
    const float* rel_bias = (const float*)d_in[6];
    const float* expand_w = (const float*)d_in[7];
    const float* gn1_s    = (const float*)d_in[8];
    const float* gn1_b    = (const float*)d_in[9];
    const float* dw_w     = (const float*)d_in[10];
    const float* gn2_s    = (const float*)d_in[11];
    const float* gn2_b    = (const float*)d_in[12];
    const float* reduce_w = (const float*)d_in[13];
    const float* gn3_s    = (const float*)d_in[14];
    const float* gn3_b    = (const float*)d_in[15];
    float* out = (float*)d_out;

    float *ab2, *ab3, *p2, *p3;
    cudaGetSymbolAddress((void**)&ab2, g_ab2);
    cudaGetSymbolAddress((void**)&ab3, g_ab3);
    cudaGetSymbolAddress((void**)&p2, g_part2);
    cudaGetSymbolAddress((void**)&p3, g_part3);

    cudaFuncSetAttribute(k_gemm1_fused, cudaFuncAttributeMaxDynamicSharedMemorySize, G1_SMEM);
    cudaFuncSetAttribute(k_gemm2_mma, cudaFuncAttributeMaxDynamicSharedMemorySize, G2_SMEM);
    cudaFuncSetAttribute(k_dw_gn2,    cudaFuncAttributeMaxDynamicSharedMemorySize, B_SMEM);
    cudaFuncSetAttribute(k_dla_out,   cudaFuncAttributeMaxDynamicSharedMemorySize, C_SMEM);

    k_xsplit<<<dim3(98, 16, BB), 256>>>(x);
    k_down<<<BB*CCH, 256>>>(x, down_w);
    k_kv  <<<dim3(4, 7, BB), 256>>>(kv_w);
    k_wqk_split<<<dim3(2, 8, BB), 256>>>(q_w);
    k_wvp <<<dim3(7, 8, BB), 256>>>(proj_w);
    k_gemm1_fused<<<dim3(49, BB), 256, G1_SMEM>>>(rel_bias);
    k_gn1_final<<<BB, 64>>>(gn1_s, gn1_b, expand_w);
    k_dw_gn2<<<dim3(196, BB), 256, B_SMEM>>>(dw_w, expand_w);
    k_stats_final<<<BB*3, 256>>>(gn2_s, gn2_b, ab2, p2, 3, 196);
    k_dla_out<<<dim3(392, BB), 256, C_SMEM>>>(dw_w, expand_w, reduce_w);
    k_stats_final<<<BB, 256>>>(gn3_s, gn3_b, ab3, p3, 1, 392);
    k_wvpsplit<<<dim3(13, 16, BB), 256>>>();
    k_wvpbias<<<BB, 512>>>(proj_b);
    k_gemm2_mma<<<dim3(8, 25, BB), 256, G2_SMEM>>>(out);
}